// round 2
// baseline (speedup 1.0000x reference)
#include <cuda_runtime.h>

#define E_TOT   100000
#define NN      50000
#define POOL_BLKS 200
#define ROWS_PER_BLK 250
#define TILE_E  64
#define GRID_MAIN ((E_TOT + TILE_E - 1) / TILE_E)
#define EA_S    132     /* padded row stride for edge_attr tile (floats) */
#define QK_S    260     /* padded row stride for qk/pooled tile (floats) */
#define SCALE   0.08838834764831845f   /* 1/sqrt(128) */

// ---------------- device scratch (no allocations allowed) ----------------
__device__ float g_partial[POOL_BLKS * 512];
__device__ float g_pooled[512];
__device__ float g_kg[512];        // [4][128]
__device__ float g_vg[512];        // [4][128]
__device__ float g_M[512];         // [4][128]  = v_g @ wo_g^T
__device__ float g_kqg[512];       // [128][4]  = wq_g^T @ k_g^T
__device__ float g_cgs[4];         // bq_g . k_g[s]
__device__ float g_C[128 * 256];   // wq_l^T @ wk_l
__device__ float g_c0[256];        // bq_l @ wk_l
__device__ float g_W2T[256 * 128]; // [j][h] = sum_m wo_l[h][m] wv_l[m][j]
__device__ float g_bias2[128];     // bv_l @ wo_l^T + bo_l

__device__ __forceinline__ float dot4(float4 a, float4 b) {
    return a.x * b.x + a.y * b.y + a.z * b.z + a.w * b.w;
}

// ---------------- kernel 1: partial column sums of global_feats ----------
__global__ void pool_partial_kernel(const float* __restrict__ gf) {
    int t = threadIdx.x;
    const float* p = gf + (size_t)blockIdx.x * ROWS_PER_BLK * 512 + t;
    float s = 0.f;
    #pragma unroll 5
    for (int r = 0; r < ROWS_PER_BLK; ++r) s += p[(size_t)r * 512];
    g_partial[blockIdx.x * 512 + t] = s;
}

// ---------------- kernel 2: C and W2T (384 blocks x 256 thr) -------------
__global__ void precompute_mats_kernel(const float* __restrict__ wq_l,
                                       const float* __restrict__ wk_l,
                                       const float* __restrict__ wv_l,
                                       const float* __restrict__ wo_l) {
    extern __shared__ float st[];     // 128*132 floats
    int b = blockIdx.x, t = threadIdx.x;
    if (b < 128) {
        // C[i][j] = sum_h wq_l[h][i] * wk_l[h][j],  i = b, j = t
        float a = 0.f;
        for (int h = 0; h < 128; ++h)
            a += __ldg(&wq_l[h * 128 + b]) * wk_l[h * 256 + t];
        g_C[b * 256 + t] = a;
    } else {
        int j = b - 128;  // 0..255
        // stage wo_l transposed: st[m*132+h] = wo_l[h][m]
        for (int idx = t; idx < 16384; idx += 256) {
            int h = idx >> 7, m = idx & 127;
            st[m * 132 + h] = wo_l[idx];
        }
        __syncthreads();
        if (t < 128) {
            float a = 0.f;
            for (int m = 0; m < 128; ++m)
                a += __ldg(&wv_l[m * 256 + j]) * st[m * 132 + t];
            g_W2T[j * 128 + t] = a;   // [j][h]
        }
    }
}

// ---------------- kernel 3: pooled + small matrices (1 block, 512 thr) ---
__global__ void precompute_small_kernel(const float* __restrict__ wk_g,
                                        const float* __restrict__ wv_g,
                                        const float* __restrict__ wo_g,
                                        const float* __restrict__ wq_g,
                                        const float* __restrict__ bk_g,
                                        const float* __restrict__ bv_g,
                                        const float* __restrict__ bq_g,
                                        const float* __restrict__ wk_l,
                                        const float* __restrict__ wo_l,
                                        const float* __restrict__ bq_l,
                                        const float* __restrict__ bv_l,
                                        const float* __restrict__ bo_l,
                                        float* __restrict__ out_pooled) {
    extern __shared__ float st[];     // 128*132 floats
    int t = threadIdx.x;

    // pooled mean + write output region
    float s = 0.f;
    for (int b = 0; b < POOL_BLKS; ++b) s += g_partial[b * 512 + t];
    s *= (1.0f / NN);
    g_pooled[t] = s;
    out_pooled[t] = s;
    __syncthreads();

    // k_g = pooled @ wk_g^T + bk_g   (stage wk_g transposed)
    for (int idx = t; idx < 16384; idx += 512) {
        int h = idx >> 7, j = idx & 127; st[j * 132 + h] = wk_g[idx];
    }
    __syncthreads();
    {
        int si = t >> 7, h = t & 127; float a = 0.f;
        for (int j = 0; j < 128; ++j) a += g_pooled[si * 128 + j] * st[j * 132 + h];
        g_kg[t] = a + bk_g[h];
    }
    __syncthreads();

    // v_g = pooled @ wv_g^T + bv_g
    for (int idx = t; idx < 16384; idx += 512) {
        int h = idx >> 7, j = idx & 127; st[j * 132 + h] = wv_g[idx];
    }
    __syncthreads();
    {
        int si = t >> 7, h = t & 127; float a = 0.f;
        for (int j = 0; j < 128; ++j) a += g_pooled[si * 128 + j] * st[j * 132 + h];
        g_vg[t] = a + bv_g[h];
    }
    __syncthreads();

    // M = v_g @ wo_g^T
    for (int idx = t; idx < 16384; idx += 512) {
        int h = idx >> 7, m = idx & 127; st[m * 132 + h] = wo_g[idx];
    }
    __syncthreads();
    {
        int si = t >> 7, h = t & 127; float a = 0.f;
        for (int m = 0; m < 128; ++m) a += g_vg[si * 128 + m] * st[m * 132 + h];
        g_M[t] = a;
    }
    __syncthreads();

    // kqg[i][s] = sum_h wq_g[h][i] * k_g[s][h] ; cgs[s] = bq_g . k_g[s]
    for (int idx = t; idx < 16384; idx += 512) {
        int h = idx >> 7, i = idx & 127; st[i * 132 + h] = wq_g[idx];
    }
    __syncthreads();
    {
        int i = t >> 2, si = t & 3; float a = 0.f;
        for (int h = 0; h < 128; ++h) a += st[i * 132 + h] * g_kg[si * 128 + h];
        g_kqg[i * 4 + si] = a;
    }
    if (t < 4) {
        float a = 0.f;
        for (int h = 0; h < 128; ++h) a += bq_g[h] * g_kg[t * 128 + h];
        g_cgs[t] = a;
    }
    __syncthreads();

    // bias2[h] = sum_m bv_l[m]*wo_l[h][m] + bo_l[h]
    for (int idx = t; idx < 16384; idx += 512) {
        int h = idx >> 7, m = idx & 127; st[m * 132 + h] = wo_l[idx];
    }
    __syncthreads();
    if (t < 128) {
        float a = 0.f;
        for (int m = 0; m < 128; ++m) a += bv_l[m] * st[m * 132 + t];
        g_bias2[t] = a + bo_l[t];
    }
    // c0[j] = sum_h bq_l[h]*wk_l[h][j]
    if (t < 256) {
        float a = 0.f;
        for (int h = 0; h < 128; ++h) a += bq_l[h] * wk_l[h * 256 + t];
        g_c0[t] = a;
    }
}

// ---------------- kernel 4: fused per-edge kernel -------------------------
__global__ void __launch_bounds__(512, 1)
main_edge_kernel(const float* __restrict__ ea_g,
                 const float* __restrict__ gf,
                 const int* __restrict__ ei,   // int32! (JAX x64 disabled)
                 const float* __restrict__ bo_g,
                 float* __restrict__ out,
                 float* __restrict__ attn_out) {
    extern __shared__ float smem[];
    float* sW  = smem;                    // 32768 floats (C, then W2T)
    float* sEA = smem + 32768;            // 64*EA_S = 8448
    float* sQK = smem + 32768 + 8448;     // 64*QK_S = 16640
    int tid = threadIdx.x;
    int e0 = blockIdx.x * TILE_E;

    // load C into smem
    {
        const float4* srcp = (const float4*)g_C;
        float4* d = (float4*)sW;
        for (int i = tid; i < 8192; i += 512) d[i] = srcp[i];
    }
    // load edge_attr tile (zero-fill OOB rows)
    for (int idx = tid; idx < 2048; idx += 512) {
        int r = idx >> 5, c = idx & 31;
        float4 v = make_float4(0.f, 0.f, 0.f, 0.f);
        if (e0 + r < E_TOT) v = ((const float4*)ea_g)[(size_t)(e0 + r) * 32 + c];
        *(float4*)&sEA[r * EA_S + c * 4] = v;
    }
    __syncthreads();

    // ---- Phase A: qk[64][256] = ea[64][128] @ C[128][256] + c0 ----
    int tx = tid & 31, ty = tid >> 5;   // tx: j-tile (8j), ty: e-tile (4e) == warp id
    float acc[4][8];
    #pragma unroll
    for (int i = 0; i < 4; ++i)
        #pragma unroll
        for (int q = 0; q < 8; ++q) acc[i][q] = 0.f;

    #pragma unroll 1
    for (int kc = 0; kc < 128; kc += 8) {
        float a[4][8];
        #pragma unroll
        for (int i = 0; i < 4; ++i) {
            float4 u = *(const float4*)&sEA[(4 * ty + i) * EA_S + kc];
            float4 v = *(const float4*)&sEA[(4 * ty + i) * EA_S + kc + 4];
            a[i][0] = u.x; a[i][1] = u.y; a[i][2] = u.z; a[i][3] = u.w;
            a[i][4] = v.x; a[i][5] = v.y; a[i][6] = v.z; a[i][7] = v.w;
        }
        #pragma unroll
        for (int kk = 0; kk < 8; ++kk) {
            float4 b0 = *(const float4*)&sW[(kc + kk) * 256 + 8 * tx];
            float4 b1 = *(const float4*)&sW[(kc + kk) * 256 + 8 * tx + 4];
            float bb[8] = {b0.x, b0.y, b0.z, b0.w, b1.x, b1.y, b1.z, b1.w};
            #pragma unroll
            for (int i = 0; i < 4; ++i)
                #pragma unroll
                for (int q = 0; q < 8; ++q)
                    acc[i][q] += a[i][kk] * bb[q];
        }
    }
    {
        float4 c0a = *(const float4*)&g_c0[8 * tx];
        float4 c0b = *(const float4*)&g_c0[8 * tx + 4];
        #pragma unroll
        for (int i = 0; i < 4; ++i) {
            *(float4*)&sQK[(4 * ty + i) * QK_S + 8 * tx] =
                make_float4(acc[i][0] + c0a.x, acc[i][1] + c0a.y,
                            acc[i][2] + c0a.z, acc[i][3] + c0a.w);
            *(float4*)&sQK[(4 * ty + i) * QK_S + 8 * tx + 4] =
                make_float4(acc[i][4] + c0b.x, acc[i][5] + c0b.y,
                            acc[i][6] + c0b.z, acc[i][7] + c0b.w);
        }
    }
    __syncwarp();  // each warp (ty) consumes exactly the qk rows it produced

    // ---- Phase B: gather + local softmax + pooled feats + global path ----
    int lane = tid & 31;
    int w = tid >> 5;
    #pragma unroll 1
    for (int r = 0; r < 4; ++r) {
        int el = 4 * w + r;
        int eg = e0 + el;
        if (eg < E_TOT) {
            int i0 = ei[eg];
            int i1 = ei[E_TOT + eg];
            const float4* srcp = (const float4*)(gf + (size_t)i0 * 512);
            const float4* dstp = (const float4*)(gf + (size_t)i1 * 512);
            float4 sv[4], dv[4];
            #pragma unroll
            for (int s2 = 0; s2 < 4; ++s2) {
                sv[s2] = srcp[s2 * 32 + lane];
                dv[s2] = dstp[s2 * 32 + lane];
            }
            float4 qlo = *(const float4*)&sQK[el * QK_S + 4 * lane];
            float4 qhi = *(const float4*)&sQK[el * QK_S + 128 + 4 * lane];
            float sc0 = dot4(qlo, sv[0]) + dot4(qhi, dv[0]);
            float sc1 = dot4(qlo, sv[1]) + dot4(qhi, dv[1]);
            float sc2 = dot4(qlo, sv[2]) + dot4(qhi, dv[2]);
            float sc3 = dot4(qlo, sv[3]) + dot4(qhi, dv[3]);
            #pragma unroll
            for (int o = 16; o > 0; o >>= 1) {
                sc0 += __shfl_xor_sync(0xFFFFFFFFu, sc0, o);
                sc1 += __shfl_xor_sync(0xFFFFFFFFu, sc1, o);
                sc2 += __shfl_xor_sync(0xFFFFFFFFu, sc2, o);
                sc3 += __shfl_xor_sync(0xFFFFFFFFu, sc3, o);
            }
            float z0 = sc0 * SCALE, z1 = sc1 * SCALE, z2 = sc2 * SCALE, z3 = sc3 * SCALE;
            float mz = fmaxf(fmaxf(z0, z1), fmaxf(z2, z3));
            float a0 = __expf(z0 - mz), a1 = __expf(z1 - mz);
            float a2 = __expf(z2 - mz), a3 = __expf(z3 - mz);
            float inv = 1.f / (a0 + a1 + a2 + a3);
            a0 *= inv; a1 *= inv; a2 *= inv; a3 *= inv;
            float4 plo, phi;
            plo.x = a0*sv[0].x + a1*sv[1].x + a2*sv[2].x + a3*sv[3].x;
            plo.y = a0*sv[0].y + a1*sv[1].y + a2*sv[2].y + a3*sv[3].y;
            plo.z = a0*sv[0].z + a1*sv[1].z + a2*sv[2].z + a3*sv[3].z;
            plo.w = a0*sv[0].w + a1*sv[1].w + a2*sv[2].w + a3*sv[3].w;
            phi.x = a0*dv[0].x + a1*dv[1].x + a2*dv[2].x + a3*dv[3].x;
            phi.y = a0*dv[0].y + a1*dv[1].y + a2*dv[2].y + a3*dv[3].y;
            phi.z = a0*dv[0].z + a1*dv[1].z + a2*dv[2].z + a3*dv[3].z;
            phi.w = a0*dv[0].w + a1*dv[1].w + a2*dv[2].w + a3*dv[3].w;
            *(float4*)&sQK[el * QK_S + 4 * lane] = plo;         // in-place pooled
            *(float4*)&sQK[el * QK_S + 128 + 4 * lane] = phi;

            // global attention path
            float4 eav = *(const float4*)&sEA[el * EA_S + 4 * lane];
            float4 kq0 = ((const float4*)g_kqg)[4 * lane + 0];
            float4 kq1 = ((const float4*)g_kqg)[4 * lane + 1];
            float4 kq2 = ((const float4*)g_kqg)[4 * lane + 2];
            float4 kq3 = ((const float4*)g_kqg)[4 * lane + 3];
            float g0 = eav.x*kq0.x + eav.y*kq1.x + eav.z*kq2.x + eav.w*kq3.x;
            float g1 = eav.x*kq0.y + eav.y*kq1.y + eav.z*kq2.y + eav.w*kq3.y;
            float g2 = eav.x*kq0.z + eav.y*kq1.z + eav.z*kq2.z + eav.w*kq3.z;
            float g3 = eav.x*kq0.w + eav.y*kq1.w + eav.z*kq2.w + eav.w*kq3.w;
            #pragma unroll
            for (int o = 16; o > 0; o >>= 1) {
                g0 += __shfl_xor_sync(0xFFFFFFFFu, g0, o);
                g1 += __shfl_xor_sync(0xFFFFFFFFu, g1, o);
                g2 += __shfl_xor_sync(0xFFFFFFFFu, g2, o);
                g3 += __shfl_xor_sync(0xFFFFFFFFu, g3, o);
            }
            float y0 = (g0 + g_cgs[0]) * SCALE, y1 = (g1 + g_cgs[1]) * SCALE;
            float y2 = (g2 + g_cgs[2]) * SCALE, y3 = (g3 + g_cgs[3]) * SCALE;
            float my = fmaxf(fmaxf(y0, y1), fmaxf(y2, y3));
            float b0 = __expf(y0 - my), b1 = __expf(y1 - my);
            float b2 = __expf(y2 - my), b3 = __expf(y3 - my);
            float binv = 1.f / (b0 + b1 + b2 + b3);
            b0 *= binv; b1 *= binv; b2 *= binv; b3 *= binv;
            if (lane == 0) {
                float* ap = attn_out + (size_t)eg * 4;
                ap[0] = b0; ap[1] = b1; ap[2] = b2; ap[3] = b3;
            }
            float4 m0 = ((const float4*)g_M)[lane];
            float4 m1 = ((const float4*)g_M)[32 + lane];
            float4 m2 = ((const float4*)g_M)[64 + lane];
            float4 m3 = ((const float4*)g_M)[96 + lane];
            float4 bo4 = ((const float4*)bo_g)[lane];
            float4 go;
            go.x = b0*m0.x + b1*m1.x + b2*m2.x + b3*m3.x + bo4.x;
            go.y = b0*m0.y + b1*m1.y + b2*m2.y + b3*m3.y + bo4.y;
            go.z = b0*m0.z + b1*m1.z + b2*m2.z + b3*m3.z + bo4.z;
            go.w = b0*m0.w + b1*m1.w + b2*m2.w + b3*m3.w + bo4.w;
            float* orow = out + (size_t)eg * 384;
            ((float4*)orow)[lane] = eav;               // out[:, 0:128] = edge_attr
            ((float4*)(orow + 256))[lane] = go;        // out[:, 256:384] = global_out
        }
    }
    __syncthreads();

    // swap in W2T
    {
        const float4* srcp = (const float4*)g_W2T;
        float4* d = (float4*)sW;
        for (int i = tid; i < 8192; i += 512) d[i] = srcp[i];
    }
    __syncthreads();

    // ---- Phase C: local_out[64][128] = pooled[64][256] @ W2T + bias2 ----
    int cx = tid & 15, cy = tid >> 4;   // cx: h-tile (8h), cy: e-tile (2e)
    int h0 = 8 * cx, eb = 2 * cy;
    float acc2[2][8];
    #pragma unroll
    for (int i = 0; i < 2; ++i)
        #pragma unroll
        for (int q = 0; q < 8; ++q) acc2[i][q] = 0.f;

    #pragma unroll 1
    for (int kc = 0; kc < 256; kc += 8) {
        float a2[2][8];
        #pragma unroll
        for (int i = 0; i < 2; ++i) {
            float4 u = *(const float4*)&sQK[(eb + i) * QK_S + kc];
            float4 v = *(const float4*)&sQK[(eb + i) * QK_S + kc + 4];
            a2[i][0] = u.x; a2[i][1] = u.y; a2[i][2] = u.z; a2[i][3] = u.w;
            a2[i][4] = v.x; a2[i][5] = v.y; a2[i][6] = v.z; a2[i][7] = v.w;
        }
        #pragma unroll
        for (int kk = 0; kk < 8; ++kk) {
            float4 b0 = *(const float4*)&sW[(kc + kk) * 128 + h0];
            float4 b1 = *(const float4*)&sW[(kc + kk) * 128 + h0 + 4];
            float bb[8] = {b0.x, b0.y, b0.z, b0.w, b1.x, b1.y, b1.z, b1.w};
            #pragma unroll
            for (int i = 0; i < 2; ++i)
                #pragma unroll
                for (int q = 0; q < 8; ++q)
                    acc2[i][q] += a2[i][kk] * bb[q];
        }
    }
    {
        float4 b2a = *(const float4*)&g_bias2[h0];
        float4 b2b = *(const float4*)&g_bias2[h0 + 4];
        #pragma unroll
        for (int i = 0; i < 2; ++i) {
            int eg = e0 + eb + i;
            if (eg < E_TOT) {
                float* orow = out + (size_t)eg * 384 + 128 + h0;
                *(float4*)orow =
                    make_float4(acc2[i][0] + b2a.x, acc2[i][1] + b2a.y,
                                acc2[i][2] + b2a.z, acc2[i][3] + b2a.w);
                *(float4*)(orow + 4) =
                    make_float4(acc2[i][4] + b2b.x, acc2[i][5] + b2b.y,
                                acc2[i][6] + b2b.z, acc2[i][7] + b2b.w);
            }
        }
    }
}

// ---------------- launch ---------------------------------------------------
extern "C" void kernel_launch(void* const* d_in, const int* in_sizes, int n_in,
                              void* d_out, int out_size) {
    const float* ea   = (const float*)d_in[0];
    const float* gf   = (const float*)d_in[1];
    const int*   ei   = (const int*)d_in[2];   // int32 (JAX default x64 disabled)
    const float* wq_l = (const float*)d_in[3];
    const float* wk_l = (const float*)d_in[4];
    const float* wv_l = (const float*)d_in[5];
    const float* bq_l = (const float*)d_in[6];
    /* bk_l (d_in[7]) cancels in softmax: constant over s */
    const float* bv_l = (const float*)d_in[8];
    const float* wo_l = (const float*)d_in[9];
    const float* bo_l = (const float*)d_in[10];
    const float* wq_g = (const float*)d_in[11];
    const float* wk_g = (const float*)d_in[12];
    const float* wv_g = (const float*)d_in[13];
    const float* bq_g = (const float*)d_in[14];
    const float* bk_g = (const float*)d_in[15];
    const float* bv_g = (const float*)d_in[16];
    const float* wo_g = (const float*)d_in[17];
    const float* bo_g = (const float*)d_in[18];

    float* out        = (float*)d_out;
    float* out_pooled = out + (size_t)E_TOT * 384;      // 38,400,000
    float* out_attn   = out_pooled + 512;               // 38,400,512

    cudaFuncSetAttribute(precompute_mats_kernel,
                         cudaFuncAttributeMaxDynamicSharedMemorySize, 67584);
    cudaFuncSetAttribute(precompute_small_kernel,
                         cudaFuncAttributeMaxDynamicSharedMemorySize, 67584);
    cudaFuncSetAttribute(main_edge_kernel,
                         cudaFuncAttributeMaxDynamicSharedMemorySize, 231424);

    pool_partial_kernel<<<POOL_BLKS, 512>>>(gf);
    precompute_mats_kernel<<<384, 256, 67584>>>(wq_l, wk_l, wv_l, wo_l);
    precompute_small_kernel<<<1, 512, 67584>>>(wk_g, wv_g, wo_g, wq_g,
                                               bk_g, bv_g, bq_g,
                                               wk_l, wo_l,
                                               bq_l, bv_l, bo_l,
                                               out_pooled);
    main_edge_kernel<<<GRID_MAIN, 512, 231424>>>(ea, gf, ei, bo_g, out, out_attn);
}

// round 5
// speedup vs baseline: 1.9152x; 1.9152x over previous
#include <cuda_runtime.h>

#define E_TOT   100000
#define NN      50000
#define POOL_BLKS 200
#define ROWS_PER_BLK 250
#define TILE_E  64
#define GRID_MAIN ((E_TOT + TILE_E - 1) / TILE_E)
#define EA_S    132     /* sEA row stride (floats), natural cols */
#define QK_S    260     /* sQK row stride (floats), natural cols */
#define SC_ROW  40      /* chunk buffer row stride (floats): 32 data + 8 pad */
#define SC_BUF  10240   /* floats per chunk buffer (256*40) */
#define SCALE   0.08838834764831845f   /* 1/sqrt(128) */

// ---------------- device scratch ----------------
__device__ float g_partial[POOL_BLKS * 512];
__device__ float g_pooled[512];
__device__ float g_kg[512];
__device__ float g_vg[512];
__device__ float g_M[512];          // [4][128] = v_g @ wo_g^T
__device__ float g_kqg[512];        // [128][4]
__device__ float g_cgs[4];
__device__ float g_Ct[256 * 128];   // [n][perm(k)] = C[k][n],  C = wq_l^T @ wk_l
__device__ float g_c0[256];         // bq_l @ wk_l
__device__ float g_W2p[128 * 256];  // [h][perm(j)] = W2[h][j] = sum_m wo_l[h][m] wv_l[m][j]
__device__ float g_bias2[128];      // bv_l @ wo_l^T + bo_l

__device__ __forceinline__ float dot4(float4 a, float4 b) {
    return a.x * b.x + a.y * b.y + a.z * b.z + a.w * b.w;
}

// pair-interleave permutation within groups of 8: (k, k+4) adjacent
__device__ __forceinline__ int permk(int k) {
    return (k >> 3) * 8 + ((k & 3) << 1) + ((k >> 2) & 1);
}

__device__ __forceinline__ void mma8(float* d, const unsigned* a, unsigned b0, unsigned b1) {
    asm volatile(
        "mma.sync.aligned.m16n8k8.row.col.f32.tf32.tf32.f32 "
        "{%0,%1,%2,%3}, {%4,%5,%6,%7}, {%8,%9}, {%0,%1,%2,%3};"
        : "+f"(d[0]), "+f"(d[1]), "+f"(d[2]), "+f"(d[3])
        : "r"(a[0]), "r"(a[1]), "r"(a[2]), "r"(a[3]), "r"(b0), "r"(b1));
}

__device__ __forceinline__ void split_tf32(float x, unsigned& b, unsigned& s) {
    b = __float_as_uint(x) & 0xFFFFE000u;
    s = __float_as_uint(x - __uint_as_float(b));
}

__device__ __forceinline__ void cpasync16(unsigned saddr, const float* g) {
    asm volatile("cp.async.ca.shared.global [%0], [%1], 16;" :: "r"(saddr), "l"(g));
}
__device__ __forceinline__ void cp_commit() {
    asm volatile("cp.async.commit_group;");
}
__device__ __forceinline__ void cp_wait1() {
    asm volatile("cp.async.wait_group 1;");
}
__device__ __forceinline__ void cp_wait0() {
    asm volatile("cp.async.wait_group 0;");
}

// ---------------- kernel 1: partial column sums of global_feats ----------
__global__ void pool_partial_kernel(const float* __restrict__ gf) {
    int t = threadIdx.x;
    const float* p = gf + (size_t)blockIdx.x * ROWS_PER_BLK * 512 + t;
    float s = 0.f;
    #pragma unroll 5
    for (int r = 0; r < ROWS_PER_BLK; ++r) s += p[(size_t)r * 512];
    g_partial[blockIdx.x * 512 + t] = s;
}

// ---------------- kernel 2: C^T and W2 (384 blocks x 256 thr) -------------
__global__ void precompute_mats_kernel(const float* __restrict__ wq_l,
                                       const float* __restrict__ wk_l,
                                       const float* __restrict__ wv_l,
                                       const float* __restrict__ wo_l) {
    extern __shared__ float st[];
    int b = blockIdx.x, t = threadIdx.x;
    if (b < 128) {
        // C[i][j] = sum_h wq_l[h][i] * wk_l[h][j], i = b, j = t
        float a = 0.f;
        for (int h = 0; h < 128; ++h)
            a += __ldg(&wq_l[h * 128 + b]) * wk_l[h * 256 + t];
        g_Ct[t * 128 + permk(b)] = a;     // [n=j][perm(k=i)]
    } else {
        int j = b - 128;  // 0..255
        for (int idx = t; idx < 16384; idx += 256) {
            int h = idx >> 7, m = idx & 127;
            st[m * 132 + h] = wo_l[idx];
        }
        __syncthreads();
        if (t < 128) {
            float a = 0.f;
            for (int m = 0; m < 128; ++m)
                a += __ldg(&wv_l[m * 256 + j]) * st[m * 132 + t];
            g_W2p[t * 256 + permk(j)] = a;   // [h=t][perm(j)]
        }
    }
}

// ---------------- kernel 3: pooled + small matrices (1 block, 512 thr) ---
__global__ void precompute_small_kernel(const float* __restrict__ wk_g,
                                        const float* __restrict__ wv_g,
                                        const float* __restrict__ wo_g,
                                        const float* __restrict__ wq_g,
                                        const float* __restrict__ bk_g,
                                        const float* __restrict__ bv_g,
                                        const float* __restrict__ bq_g,
                                        const float* __restrict__ wk_l,
                                        const float* __restrict__ wo_l,
                                        const float* __restrict__ bq_l,
                                        const float* __restrict__ bv_l,
                                        const float* __restrict__ bo_l,
                                        float* __restrict__ out_pooled) {
    extern __shared__ float st[];
    int t = threadIdx.x;

    float s = 0.f;
    for (int b = 0; b < POOL_BLKS; ++b) s += g_partial[b * 512 + t];
    s *= (1.0f / NN);
    g_pooled[t] = s;
    out_pooled[t] = s;
    __syncthreads();

    for (int idx = t; idx < 16384; idx += 512) {
        int h = idx >> 7, j = idx & 127; st[j * 132 + h] = wk_g[idx];
    }
    __syncthreads();
    {
        int si = t >> 7, h = t & 127; float a = 0.f;
        for (int j = 0; j < 128; ++j) a += g_pooled[si * 128 + j] * st[j * 132 + h];
        g_kg[t] = a + bk_g[h];
    }
    __syncthreads();

    for (int idx = t; idx < 16384; idx += 512) {
        int h = idx >> 7, j = idx & 127; st[j * 132 + h] = wv_g[idx];
    }
    __syncthreads();
    {
        int si = t >> 7, h = t & 127; float a = 0.f;
        for (int j = 0; j < 128; ++j) a += g_pooled[si * 128 + j] * st[j * 132 + h];
        g_vg[t] = a + bv_g[h];
    }
    __syncthreads();

    for (int idx = t; idx < 16384; idx += 512) {
        int h = idx >> 7, m = idx & 127; st[m * 132 + h] = wo_g[idx];
    }
    __syncthreads();
    {
        int si = t >> 7, h = t & 127; float a = 0.f;
        for (int m = 0; m < 128; ++m) a += g_vg[si * 128 + m] * st[m * 132 + h];
        g_M[t] = a;
    }
    __syncthreads();

    for (int idx = t; idx < 16384; idx += 512) {
        int h = idx >> 7, i = idx & 127; st[i * 132 + h] = wq_g[idx];
    }
    __syncthreads();
    {
        int i = t >> 2, si = t & 3; float a = 0.f;
        for (int h = 0; h < 128; ++h) a += st[i * 132 + h] * g_kg[si * 128 + h];
        g_kqg[i * 4 + si] = a;
    }
    if (t < 4) {
        float a = 0.f;
        for (int h = 0; h < 128; ++h) a += bq_g[h] * g_kg[t * 128 + h];
        g_cgs[t] = a;
    }
    __syncthreads();

    for (int idx = t; idx < 16384; idx += 512) {
        int h = idx >> 7, m = idx & 127; st[m * 132 + h] = wo_l[idx];
    }
    __syncthreads();
    if (t < 128) {
        float a = 0.f;
        for (int m = 0; m < 128; ++m) a += bv_l[m] * st[m * 132 + t];
        g_bias2[t] = a + bo_l[t];
    }
    if (t < 256) {
        float a = 0.f;
        for (int h = 0; h < 128; ++h) a += bq_l[h] * wk_l[h * 256 + t];
        g_c0[t] = a;
    }
}

// ---------------- kernel 4: fused per-edge kernel -------------------------
__global__ void __launch_bounds__(512, 1)
main_edge_kernel(const float* __restrict__ ea_g,
                 const float* __restrict__ gf,
                 const int* __restrict__ ei,
                 const float* __restrict__ bo_g,
                 float* __restrict__ out,
                 float* __restrict__ attn_out) {
    extern __shared__ float smem[];
    float* sC  = smem;                      // 2 x SC_BUF floats (chunk double-buffer)
    float* sEA = smem + 2 * SC_BUF;         // 64*132 = 8448
    float* sQK = smem + 2 * SC_BUF + 8448;  // 64*260 = 16640
    const int tid  = threadIdx.x;
    const int wid  = tid >> 5;
    const int lane = tid & 31;
    const int g    = lane >> 2;    // 0..7
    const int t4   = lane & 3;     // 0..3
    const int e0   = blockIdx.x * TILE_E;
    const unsigned smem_b = (unsigned)__cvta_generic_to_shared(smem);

    // ---- prefetch C chunk 0, stage edge_attr tile, prefetch C chunk 1 ----
    #pragma unroll
    for (int i = 0; i < 4; ++i) {
        int e = tid + 512 * i;
        int n = e >> 3, q = e & 7;
        cpasync16(smem_b + n * (SC_ROW * 4) + q * 16, g_Ct + n * 128 + 0 + q * 4);
    }
    cp_commit();

    for (int idx = tid; idx < 2048; idx += 512) {
        int r = idx >> 5, c = idx & 31;
        float4 v = make_float4(0.f, 0.f, 0.f, 0.f);
        if (e0 + r < E_TOT) v = ((const float4*)ea_g)[(size_t)(e0 + r) * 32 + c];
        *(float4*)&sEA[r * EA_S + c * 4] = v;
    }

    #pragma unroll
    for (int i = 0; i < 4; ++i) {
        int e = tid + 512 * i;
        int n = e >> 3, q = e & 7;
        cpasync16(smem_b + SC_BUF * 4 + n * (SC_ROW * 4) + q * 16,
                  g_Ct + n * 128 + 32 + q * 4);
    }
    cp_commit();

    // ---- Phase A: qk[64][256] = ea[64][128] @ C + c0  (tf32 3-term mma) ----
    {
        const int wm = wid >> 3;          // 0..1
        const int wn = wid & 7;           // 0..7
        const int m0 = wm * 32;
        const int n0 = wn * 32;
        float acc[2][4][4];
        #pragma unroll
        for (int am = 0; am < 2; ++am)
            #pragma unroll
            for (int bn = 0; bn < 4; ++bn)
                #pragma unroll
                for (int q = 0; q < 4; ++q) acc[am][bn][q] = 0.f;

        #pragma unroll 1
        for (int cc = 0; cc < 4; ++cc) {
            if (cc < 3) cp_wait1(); else cp_wait0();
            __syncthreads();
            const float* sc = sC + ((cc & 1) ? SC_BUF : 0);

            #pragma unroll
            for (int ks = 0; ks < 4; ++ks) {
                const int kb = cc * 32 + ks * 8;
                unsigned Ab[2][4], As[2][4];
                #pragma unroll
                for (int am = 0; am < 2; ++am) {
                    int R = m0 + 16 * am;
                    float a0 = sEA[(R + g)     * EA_S + kb + t4];
                    float a1 = sEA[(R + g + 8) * EA_S + kb + t4];
                    float a2 = sEA[(R + g)     * EA_S + kb + t4 + 4];
                    float a3 = sEA[(R + g + 8) * EA_S + kb + t4 + 4];
                    split_tf32(a0, Ab[am][0], As[am][0]);
                    split_tf32(a1, Ab[am][1], As[am][1]);
                    split_tf32(a2, Ab[am][2], As[am][2]);
                    split_tf32(a3, Ab[am][3], As[am][3]);
                }
                #pragma unroll
                for (int bn = 0; bn < 4; ++bn) {
                    uint2 bp = *(const uint2*)&sc[(n0 + 8 * bn + g) * SC_ROW + ks * 8 + t4 * 2];
                    unsigned b0b, b0s, b1b, b1s;
                    split_tf32(__uint_as_float(bp.x), b0b, b0s);
                    split_tf32(__uint_as_float(bp.y), b1b, b1s);
                    #pragma unroll
                    for (int am = 0; am < 2; ++am) {
                        mma8(acc[am][bn], As[am], b0b, b1b);
                        mma8(acc[am][bn], Ab[am], b0s, b1s);
                        mma8(acc[am][bn], Ab[am], b0b, b1b);
                    }
                }
            }
            __syncthreads();
            // prefetch C chunk cc+2 into the buffer just freed (parity cc&1)
            if (cc + 2 < 4) {
                #pragma unroll
                for (int i = 0; i < 4; ++i) {
                    int e = tid + 512 * i;
                    int n = e >> 3, q = e & 7;
                    cpasync16(smem_b + ((cc & 1) ? SC_BUF * 4 : 0) + n * (SC_ROW * 4) + q * 16,
                              g_Ct + n * 128 + (cc + 2) * 32 + q * 4);
                }
                cp_commit();
            }
        }

        // epilogue: qk + c0 -> sQK
        #pragma unroll
        for (int am = 0; am < 2; ++am) {
            #pragma unroll
            for (int bn = 0; bn < 4; ++bn) {
                int col = n0 + 8 * bn + 2 * t4;
                float2 c0v = *(const float2*)&g_c0[col];
                int r1 = m0 + 16 * am + g;
                *(float2*)&sQK[r1 * QK_S + col] =
                    make_float2(acc[am][bn][0] + c0v.x, acc[am][bn][1] + c0v.y);
                *(float2*)&sQK[(r1 + 8) * QK_S + col] =
                    make_float2(acc[am][bn][2] + c0v.x, acc[am][bn][3] + c0v.y);
            }
        }
    }
    __syncthreads();

    // ---- prefetch W2 chunks 0,1 (overlaps Phase B gathers) ----
    #pragma unroll
    for (int i = 0; i < 2; ++i) {
        int e = tid + 512 * i;
        int n = e >> 3, q = e & 7;
        cpasync16(smem_b + n * (SC_ROW * 4) + q * 16, g_W2p + n * 256 + 0 + q * 4);
    }
    cp_commit();
    #pragma unroll
    for (int i = 0; i < 2; ++i) {
        int e = tid + 512 * i;
        int n = e >> 3, q = e & 7;
        cpasync16(smem_b + SC_BUF * 4 + n * (SC_ROW * 4) + q * 16,
                  g_W2p + n * 256 + 32 + q * 4);
    }
    cp_commit();

    // ---- Phase B: gather + local softmax + pooled feats + global path ----
    #pragma unroll 1
    for (int r = 0; r < 4; ++r) {
        int el = 4 * wid + r;
        int eg = e0 + el;
        if (eg < E_TOT) {
            int i0 = ei[eg];
            int i1 = ei[E_TOT + eg];
            const float4* srcp = (const float4*)(gf + (size_t)i0 * 512);
            const float4* dstp = (const float4*)(gf + (size_t)i1 * 512);
            float4 sv[4], dv[4];
            #pragma unroll
            for (int s2 = 0; s2 < 4; ++s2) {
                sv[s2] = srcp[s2 * 32 + lane];
                dv[s2] = dstp[s2 * 32 + lane];
            }
            float4 qlo = *(const float4*)&sQK[el * QK_S + 4 * lane];
            float4 qhi = *(const float4*)&sQK[el * QK_S + 128 + 4 * lane];
            float sc0 = dot4(qlo, sv[0]) + dot4(qhi, dv[0]);
            float sc1 = dot4(qlo, sv[1]) + dot4(qhi, dv[1]);
            float sc2 = dot4(qlo, sv[2]) + dot4(qhi, dv[2]);
            float sc3 = dot4(qlo, sv[3]) + dot4(qhi, dv[3]);
            #pragma unroll
            for (int o = 16; o > 0; o >>= 1) {
                sc0 += __shfl_xor_sync(0xFFFFFFFFu, sc0, o);
                sc1 += __shfl_xor_sync(0xFFFFFFFFu, sc1, o);
                sc2 += __shfl_xor_sync(0xFFFFFFFFu, sc2, o);
                sc3 += __shfl_xor_sync(0xFFFFFFFFu, sc3, o);
            }
            float z0 = sc0 * SCALE, z1 = sc1 * SCALE, z2 = sc2 * SCALE, z3 = sc3 * SCALE;
            float mz = fmaxf(fmaxf(z0, z1), fmaxf(z2, z3));
            float a0 = __expf(z0 - mz), a1 = __expf(z1 - mz);
            float a2 = __expf(z2 - mz), a3 = __expf(z3 - mz);
            float inv = 1.f / (a0 + a1 + a2 + a3);
            a0 *= inv; a1 *= inv; a2 *= inv; a3 *= inv;
            float4 plo, phi;
            plo.x = a0*sv[0].x + a1*sv[1].x + a2*sv[2].x + a3*sv[3].x;
            plo.y = a0*sv[0].y + a1*sv[1].y + a2*sv[2].y + a3*sv[3].y;
            plo.z = a0*sv[0].z + a1*sv[1].z + a2*sv[2].z + a3*sv[3].z;
            plo.w = a0*sv[0].w + a1*sv[1].w + a2*sv[2].w + a3*sv[3].w;
            phi.x = a0*dv[0].x + a1*dv[1].x + a2*dv[2].x + a3*dv[3].x;
            phi.y = a0*dv[0].y + a1*dv[1].y + a2*dv[2].y + a3*dv[3].y;
            phi.z = a0*dv[0].z + a1*dv[1].z + a2*dv[2].z + a3*dv[3].z;
            phi.w = a0*dv[0].w + a1*dv[1].w + a2*dv[2].w + a3*dv[3].w;
            *(float4*)&sQK[el * QK_S + 4 * lane] = plo;
            *(float4*)&sQK[el * QK_S + 128 + 4 * lane] = phi;

            float4 eav = *(const float4*)&sEA[el * EA_S + 4 * lane];
            float4 kq0 = ((const float4*)g_kqg)[4 * lane + 0];
            float4 kq1 = ((const float4*)g_kqg)[4 * lane + 1];
            float4 kq2 = ((const float4*)g_kqg)[4 * lane + 2];
            float4 kq3 = ((const float4*)g_kqg)[4 * lane + 3];
            float g0 = eav.x*kq0.x + eav.y*kq1.x + eav.z*kq2.x + eav.w*kq3.x;
            float g1 = eav.x*kq0.y + eav.y*kq1.y + eav.z*kq2.y + eav.w*kq3.y;
            float g2 = eav.x*kq0.z + eav.y*kq1.z + eav.z*kq2.z + eav.w*kq3.z;
            float g3 = eav.x*kq0.w + eav.y*kq1.w + eav.z*kq2.w + eav.w*kq3.w;
            #pragma unroll
            for (int o = 16; o > 0; o >>= 1) {
                g0 += __shfl_xor_sync(0xFFFFFFFFu, g0, o);
                g1 += __shfl_xor_sync(0xFFFFFFFFu, g1, o);
                g2 += __shfl_xor_sync(0xFFFFFFFFu, g2, o);
                g3 += __shfl_xor_sync(0xFFFFFFFFu, g3, o);
            }
            float y0 = (g0 + g_cgs[0]) * SCALE, y1 = (g1 + g_cgs[1]) * SCALE;
            float y2 = (g2 + g_cgs[2]) * SCALE, y3 = (g3 + g_cgs[3]) * SCALE;
            float my = fmaxf(fmaxf(y0, y1), fmaxf(y2, y3));
            float b0 = __expf(y0 - my), b1 = __expf(y1 - my);
            float b2 = __expf(y2 - my), b3 = __expf(y3 - my);
            float binv = 1.f / (b0 + b1 + b2 + b3);
            b0 *= binv; b1 *= binv; b2 *= binv; b3 *= binv;
            if (lane == 0) {
                float* ap = attn_out + (size_t)eg * 4;
                ap[0] = b0; ap[1] = b1; ap[2] = b2; ap[3] = b3;
            }
            float4 m0v = ((const float4*)g_M)[lane];
            float4 m1v = ((const float4*)g_M)[32 + lane];
            float4 m2v = ((const float4*)g_M)[64 + lane];
            float4 m3v = ((const float4*)g_M)[96 + lane];
            float4 bo4 = ((const float4*)bo_g)[lane];
            float4 go;
            go.x = b0*m0v.x + b1*m1v.x + b2*m2v.x + b3*m3v.x + bo4.x;
            go.y = b0*m0v.y + b1*m1v.y + b2*m2v.y + b3*m3v.y + bo4.y;
            go.z = b0*m0v.z + b1*m1v.z + b2*m2v.z + b3*m3v.z + bo4.z;
            go.w = b0*m0v.w + b1*m1v.w + b2*m2v.w + b3*m3v.w + bo4.w;
            float* orow = out + (size_t)eg * 384;
            ((float4*)orow)[lane] = eav;
            ((float4*)(orow + 256))[lane] = go;
        }
    }
    __syncthreads();

    // ---- Phase C: local_out[64][128] = pooled[64][256] @ W2^T + bias2 ----
    {
        const int cm = wid >> 2;         // 0..3
        const int cn = wid & 3;          // 0..3
        const int m0 = cm * 16;
        const int n0 = cn * 32;
        float acc[4][4];
        #pragma unroll
        for (int bn = 0; bn < 4; ++bn)
            #pragma unroll
            for (int q = 0; q < 4; ++q) acc[bn][q] = 0.f;

        #pragma unroll 1
        for (int cc = 0; cc < 8; ++cc) {
            if (cc < 7) cp_wait1(); else cp_wait0();
            __syncthreads();
            const float* sc = sC + ((cc & 1) ? SC_BUF : 0);

            #pragma unroll
            for (int ks = 0; ks < 4; ++ks) {
                const int kb = cc * 32 + ks * 8;
                unsigned Ab[4], As[4];
                {
                    float a0 = sQK[(m0 + g)     * QK_S + kb + t4];
                    float a1 = sQK[(m0 + g + 8) * QK_S + kb + t4];
                    float a2 = sQK[(m0 + g)     * QK_S + kb + t4 + 4];
                    float a3 = sQK[(m0 + g + 8) * QK_S + kb + t4 + 4];
                    split_tf32(a0, Ab[0], As[0]);
                    split_tf32(a1, Ab[1], As[1]);
                    split_tf32(a2, Ab[2], As[2]);
                    split_tf32(a3, Ab[3], As[3]);
                }
                #pragma unroll
                for (int bn = 0; bn < 4; ++bn) {
                    uint2 bp = *(const uint2*)&sc[(n0 + 8 * bn + g) * SC_ROW + ks * 8 + t4 * 2];
                    unsigned b0b, b0s, b1b, b1s;
                    split_tf32(__uint_as_float(bp.x), b0b, b0s);
                    split_tf32(__uint_as_float(bp.y), b1b, b1s);
                    mma8(acc[bn], As, b0b, b1b);
                    mma8(acc[bn], Ab, b0s, b1s);
                    mma8(acc[bn], Ab, b0b, b1b);
                }
            }
            __syncthreads();
            // prefetch W2 chunk cc+2 into the buffer just freed (parity cc&1)
            if (cc + 2 < 8) {
                #pragma unroll
                for (int i = 0; i < 2; ++i) {
                    int e = tid + 512 * i;
                    int n = e >> 3, q = e & 7;
                    cpasync16(smem_b + ((cc & 1) ? SC_BUF * 4 : 0) + n * (SC_ROW * 4) + q * 16,
                              g_W2p + n * 256 + (cc + 2) * 32 + q * 4);
                }
                cp_commit();
            }
        }

        // epilogue: + bias2 -> out[:, 128:256]
        #pragma unroll
        for (int bn = 0; bn < 4; ++bn) {
            int h = n0 + 8 * bn + 2 * t4;
            float2 bv = *(const float2*)&g_bias2[h];
            int e1 = e0 + m0 + g;
            if (e1 < E_TOT) {
                *(float2*)&out[(size_t)e1 * 384 + 128 + h] =
                    make_float2(acc[bn][0] + bv.x, acc[bn][1] + bv.y);
            }
            int e2 = e1 + 8;
            if (e2 < E_TOT) {
                *(float2*)&out[(size_t)e2 * 384 + 128 + h] =
                    make_float2(acc[bn][2] + bv.x, acc[bn][3] + bv.y);
            }
        }
    }
}

// ---------------- launch ---------------------------------------------------
extern "C" void kernel_launch(void* const* d_in, const int* in_sizes, int n_in,
                              void* d_out, int out_size) {
    const float* ea   = (const float*)d_in[0];
    const float* gf   = (const float*)d_in[1];
    const int*   ei   = (const int*)d_in[2];
    const float* wq_l = (const float*)d_in[3];
    const float* wk_l = (const float*)d_in[4];
    const float* wv_l = (const float*)d_in[5];
    const float* bq_l = (const float*)d_in[6];
    const float* bv_l = (const float*)d_in[8];
    const float* wo_l = (const float*)d_in[9];
    const float* bo_l = (const float*)d_in[10];
    const float* wq_g = (const float*)d_in[11];
    const float* wk_g = (const float*)d_in[12];
    const float* wv_g = (const float*)d_in[13];
    const float* bq_g = (const float*)d_in[14];
    const float* bk_g = (const float*)d_in[15];
    const float* bv_g = (const float*)d_in[16];
    const float* wo_g = (const float*)d_in[17];
    const float* bo_g = (const float*)d_in[18];

    float* out        = (float*)d_out;
    float* out_pooled = out + (size_t)E_TOT * 384;
    float* out_attn   = out_pooled + 512;

    const int MAIN_SMEM = (2 * SC_BUF + 8448 + 16640) * 4;   // 182272 B

    cudaFuncSetAttribute(precompute_mats_kernel,
                         cudaFuncAttributeMaxDynamicSharedMemorySize, 67584);
    cudaFuncSetAttribute(precompute_small_kernel,
                         cudaFuncAttributeMaxDynamicSharedMemorySize, 67584);
    cudaFuncSetAttribute(main_edge_kernel,
                         cudaFuncAttributeMaxDynamicSharedMemorySize, MAIN_SMEM);

    pool_partial_kernel<<<POOL_BLKS, 512>>>(gf);
    precompute_mats_kernel<<<384, 256, 67584>>>(wq_l, wk_l, wv_l, wo_l);
    precompute_small_kernel<<<1, 512, 67584>>>(wk_g, wv_g, wo_g, wq_g,
                                               bk_g, bv_g, bq_g,
                                               wk_l, wo_l,
                                               bq_l, bv_l, bo_l,
                                               out_pooled);
    main_edge_kernel<<<GRID_MAIN, 512, MAIN_SMEM>>>(ea, gf, ei, bo_g, out, out_attn);
}

// round 6
// speedup vs baseline: 2.3012x; 1.2015x over previous
#include <cuda_runtime.h>

#define E_TOT   100000
#define NN      50000
#define POOL_BLKS 200
#define ROWS_PER_BLK 250
#define TILE_E  64
#define GRID_MAIN ((E_TOT + TILE_E - 1) / TILE_E)
#define EA_S    132     /* sEA row stride (floats) */
#define QK_S    260     /* sQK row stride (floats) */
#define SCALE   0.08838834764831845f   /* 1/sqrt(128) */

// ---------------- device scratch ----------------
__device__ float g_partial[POOL_BLKS * 512];
__device__ float g_pooled[512];
__device__ float g_kg[512];
__device__ float g_vg[512];
__device__ float g_M[512];          // [4][128] = v_g @ wo_g^T
__device__ float g_kqg[512];        // [128][4]
__device__ float g_cgs[4];
__device__ float g_Ct[256 * 128];   // [n][perm(k)] = C[k][n],  C = wq_l^T @ wk_l
__device__ float g_c0[256];         // bq_l @ wk_l
__device__ float g_W2p[128 * 256];  // [h][perm(j)] = W2[h][j]
__device__ float g_bias2[128];      // bv_l @ wo_l^T + bo_l

__device__ __forceinline__ float dot4(float4 a, float4 b) {
    return a.x * b.x + a.y * b.y + a.z * b.z + a.w * b.w;
}

// pair-interleave permutation within groups of 8: (k, k+4) adjacent
__device__ __forceinline__ int permk(int k) {
    return (k >> 3) * 8 + ((k & 3) << 1) + ((k >> 2) & 1);
}

__device__ __forceinline__ void mma8(float* d, const unsigned* a, unsigned b0, unsigned b1) {
    asm volatile(
        "mma.sync.aligned.m16n8k8.row.col.f32.tf32.tf32.f32 "
        "{%0,%1,%2,%3}, {%4,%5,%6,%7}, {%8,%9}, {%0,%1,%2,%3};"
        : "+f"(d[0]), "+f"(d[1]), "+f"(d[2]), "+f"(d[3])
        : "r"(a[0]), "r"(a[1]), "r"(a[2]), "r"(a[3]), "r"(b0), "r"(b1));
}

__device__ __forceinline__ void split_tf32(float x, unsigned& b, unsigned& s) {
    b = __float_as_uint(x) & 0xFFFFE000u;
    s = __float_as_uint(x - __uint_as_float(b));
}

// ---------------- kernel 1: pool partials + C^T + W2 + c0 + bias2 --------
// blocks 0..199: pool partial; 200..327: C rows; 328..583: W2 rows;
// 584: c0; 585: bias2.  512 threads each.
__global__ void k1_precompute(const float* __restrict__ gf,
                              const float* __restrict__ wq_l,
                              const float* __restrict__ wk_l,
                              const float* __restrict__ wv_l,
                              const float* __restrict__ wo_l,
                              const float* __restrict__ bq_l,
                              const float* __restrict__ bv_l,
                              const float* __restrict__ bo_l) {
    extern __shared__ float st[];
    int b = blockIdx.x, t = threadIdx.x;
    if (b < POOL_BLKS) {
        const float* p = gf + (size_t)b * ROWS_PER_BLK * 512 + t;
        float s = 0.f;
        #pragma unroll 5
        for (int r = 0; r < ROWS_PER_BLK; ++r) s += p[(size_t)r * 512];
        g_partial[b * 512 + t] = s;
    } else if (b < 328) {
        int i = b - 200;            // C row 0..127
        if (t < 256) {
            float a = 0.f;
            for (int h = 0; h < 128; ++h)
                a += __ldg(&wq_l[h * 128 + i]) * wk_l[h * 256 + t];
            g_Ct[t * 128 + permk(i)] = a;
        }
    } else if (b < 584) {
        int j = b - 328;            // W2 col 0..255
        for (int idx = t; idx < 16384; idx += 512) {
            int h = idx >> 7, m = idx & 127;
            st[m * 132 + h] = wo_l[idx];
        }
        __syncthreads();
        if (t < 128) {
            float a = 0.f;
            for (int m = 0; m < 128; ++m)
                a += __ldg(&wv_l[m * 256 + j]) * st[m * 132 + t];
            g_W2p[t * 256 + permk(j)] = a;
        }
    } else if (b == 584) {
        if (t < 256) {
            float a = 0.f;
            for (int h = 0; h < 128; ++h) a += bq_l[h] * wk_l[h * 256 + t];
            g_c0[t] = a;
        }
    } else {
        for (int idx = t; idx < 16384; idx += 512) {
            int h = idx >> 7, m = idx & 127;
            st[m * 132 + h] = wo_l[idx];
        }
        __syncthreads();
        if (t < 128) {
            float a = 0.f;
            for (int m = 0; m < 128; ++m) a += bv_l[m] * st[m * 132 + t];
            g_bias2[t] = a + bo_l[t];
        }
    }
}

// ---------------- kernel 2: pooled + global-path small matrices ----------
__global__ void k2_small(const float* __restrict__ wk_g,
                         const float* __restrict__ wv_g,
                         const float* __restrict__ wo_g,
                         const float* __restrict__ wq_g,
                         const float* __restrict__ bk_g,
                         const float* __restrict__ bv_g,
                         const float* __restrict__ bq_g,
                         float* __restrict__ out_pooled) {
    extern __shared__ float st[];
    int t = threadIdx.x;

    float s = 0.f;
    for (int b = 0; b < POOL_BLKS; ++b) s += g_partial[b * 512 + t];
    s *= (1.0f / NN);
    g_pooled[t] = s;
    out_pooled[t] = s;
    __syncthreads();

    // k_g = pooled @ wk_g^T + bk_g
    for (int idx = t; idx < 16384; idx += 512) {
        int h = idx >> 7, j = idx & 127; st[j * 132 + h] = wk_g[idx];
    }
    __syncthreads();
    {
        int si = t >> 7, h = t & 127; float a = 0.f;
        for (int j = 0; j < 128; ++j) a += g_pooled[si * 128 + j] * st[j * 132 + h];
        g_kg[t] = a + bk_g[h];
    }
    __syncthreads();

    // v_g = pooled @ wv_g^T + bv_g
    for (int idx = t; idx < 16384; idx += 512) {
        int h = idx >> 7, j = idx & 127; st[j * 132 + h] = wv_g[idx];
    }
    __syncthreads();
    {
        int si = t >> 7, h = t & 127; float a = 0.f;
        for (int j = 0; j < 128; ++j) a += g_pooled[si * 128 + j] * st[j * 132 + h];
        g_vg[t] = a + bv_g[h];
    }
    __syncthreads();

    // M = v_g @ wo_g^T
    for (int idx = t; idx < 16384; idx += 512) {
        int h = idx >> 7, m = idx & 127; st[m * 132 + h] = wo_g[idx];
    }
    __syncthreads();
    {
        int si = t >> 7, h = t & 127; float a = 0.f;
        for (int m = 0; m < 128; ++m) a += g_vg[si * 128 + m] * st[m * 132 + h];
        g_M[t] = a;
    }
    __syncthreads();

    // kqg[i][s] = sum_h wq_g[h][i] * k_g[s][h] ; cgs[s] = bq_g . k_g[s]
    for (int idx = t; idx < 16384; idx += 512) {
        int h = idx >> 7, i = idx & 127; st[i * 132 + h] = wq_g[idx];
    }
    __syncthreads();
    {
        int i = t >> 2, si = t & 3; float a = 0.f;
        for (int h = 0; h < 128; ++h) a += st[i * 132 + h] * g_kg[si * 128 + h];
        g_kqg[i * 4 + si] = a;
    }
    if (t < 4) {
        float a = 0.f;
        for (int h = 0; h < 128; ++h) a += bq_g[h] * g_kg[t * 128 + h];
        g_cgs[t] = a;
    }
}

// ---------------- kernel 3: fused per-edge kernel (256 thr, 2 CTA/SM) ----
__global__ void __launch_bounds__(256, 2)
main_edge_kernel(const float* __restrict__ ea_g,
                 const float* __restrict__ gf,
                 const int* __restrict__ ei,
                 const float* __restrict__ bo_g,
                 float* __restrict__ out,
                 float* __restrict__ attn_out) {
    extern __shared__ float smem[];
    float* sEA = smem;            // 64*132 = 8448 floats
    float* sQK = smem + 8448;     // 64*260 = 16640 floats
    const int tid  = threadIdx.x;
    const int wid  = tid >> 5;    // 0..7
    const int lane = tid & 31;
    const int g    = lane >> 2;   // 0..7
    const int t4   = lane & 3;    // 0..3
    const int e0   = blockIdx.x * TILE_E;

    // stage edge_attr tile (zero-fill OOB rows)
    for (int idx = tid; idx < 2048; idx += 256) {
        int r = idx >> 5, c = idx & 31;
        float4 v = make_float4(0.f, 0.f, 0.f, 0.f);
        if (e0 + r < E_TOT) v = ((const float4*)ea_g)[(size_t)(e0 + r) * 32 + c];
        *(float4*)&sEA[r * EA_S + c * 4] = v;
    }
    __syncthreads();

    // ---- Phase A: qk[64][256] = ea[64][128] @ C + c0 (tf32 3-term mma) ----
    // warps: 2m x 4n; warp tile m32 x n64; B direct from L2.
    {
        const int wm = wid >> 2;          // 0..1
        const int wn = wid & 3;           // 0..3
        const int m0 = wm * 32;
        const int n0 = wn * 64;
        float acc[2][8][4];
        #pragma unroll
        for (int am = 0; am < 2; ++am)
            #pragma unroll
            for (int bn = 0; bn < 8; ++bn)
                #pragma unroll
                for (int q = 0; q < 4; ++q) acc[am][bn][q] = 0.f;

        #pragma unroll 1
        for (int kb = 0; kb < 128; kb += 8) {
            // issue all 8 B-fragment loads first (L2 latency overlap)
            uint2 bp[8];
            #pragma unroll
            for (int bn = 0; bn < 8; ++bn)
                bp[bn] = __ldg((const uint2*)&g_Ct[(n0 + 8 * bn + g) * 128 + kb + 2 * t4]);

            unsigned Ab[2][4], As[2][4];
            #pragma unroll
            for (int am = 0; am < 2; ++am) {
                int R = m0 + 16 * am;
                float a0 = sEA[(R + g)     * EA_S + kb + t4];
                float a1 = sEA[(R + g + 8) * EA_S + kb + t4];
                float a2 = sEA[(R + g)     * EA_S + kb + t4 + 4];
                float a3 = sEA[(R + g + 8) * EA_S + kb + t4 + 4];
                split_tf32(a0, Ab[am][0], As[am][0]);
                split_tf32(a1, Ab[am][1], As[am][1]);
                split_tf32(a2, Ab[am][2], As[am][2]);
                split_tf32(a3, Ab[am][3], As[am][3]);
            }
            #pragma unroll
            for (int bn = 0; bn < 8; ++bn) {
                unsigned b0b, b0s, b1b, b1s;
                split_tf32(__uint_as_float(bp[bn].x), b0b, b0s);
                split_tf32(__uint_as_float(bp[bn].y), b1b, b1s);
                #pragma unroll
                for (int am = 0; am < 2; ++am) {
                    mma8(acc[am][bn], As[am], b0b, b1b);
                    mma8(acc[am][bn], Ab[am], b0s, b1s);
                    mma8(acc[am][bn], Ab[am], b0b, b1b);
                }
            }
        }

        // epilogue: qk + c0 -> sQK
        #pragma unroll
        for (int am = 0; am < 2; ++am) {
            #pragma unroll
            for (int bn = 0; bn < 8; ++bn) {
                int col = n0 + 8 * bn + 2 * t4;
                float2 c0v = *(const float2*)&g_c0[col];
                int r1 = m0 + 16 * am + g;
                *(float2*)&sQK[r1 * QK_S + col] =
                    make_float2(acc[am][bn][0] + c0v.x, acc[am][bn][1] + c0v.y);
                *(float2*)&sQK[(r1 + 8) * QK_S + col] =
                    make_float2(acc[am][bn][2] + c0v.x, acc[am][bn][3] + c0v.y);
            }
        }
    }
    __syncthreads();

    // ---- Phase B: gather + local softmax + pooled feats + global path ----
    #pragma unroll 1
    for (int r = 0; r < 8; ++r) {
        int el = 8 * wid + r;
        int eg = e0 + el;
        if (eg < E_TOT) {
            int i0 = ei[eg];
            int i1 = ei[E_TOT + eg];
            const float4* srcp = (const float4*)(gf + (size_t)i0 * 512);
            const float4* dstp = (const float4*)(gf + (size_t)i1 * 512);
            float4 sv[4], dv[4];
            #pragma unroll
            for (int s2 = 0; s2 < 4; ++s2) {
                sv[s2] = srcp[s2 * 32 + lane];
                dv[s2] = dstp[s2 * 32 + lane];
            }
            float4 qlo = *(const float4*)&sQK[el * QK_S + 4 * lane];
            float4 qhi = *(const float4*)&sQK[el * QK_S + 128 + 4 * lane];
            float sc0 = dot4(qlo, sv[0]) + dot4(qhi, dv[0]);
            float sc1 = dot4(qlo, sv[1]) + dot4(qhi, dv[1]);
            float sc2 = dot4(qlo, sv[2]) + dot4(qhi, dv[2]);
            float sc3 = dot4(qlo, sv[3]) + dot4(qhi, dv[3]);
            #pragma unroll
            for (int o = 16; o > 0; o >>= 1) {
                sc0 += __shfl_xor_sync(0xFFFFFFFFu, sc0, o);
                sc1 += __shfl_xor_sync(0xFFFFFFFFu, sc1, o);
                sc2 += __shfl_xor_sync(0xFFFFFFFFu, sc2, o);
                sc3 += __shfl_xor_sync(0xFFFFFFFFu, sc3, o);
            }
            float z0 = sc0 * SCALE, z1 = sc1 * SCALE, z2 = sc2 * SCALE, z3 = sc3 * SCALE;
            float mz = fmaxf(fmaxf(z0, z1), fmaxf(z2, z3));
            float a0 = __expf(z0 - mz), a1 = __expf(z1 - mz);
            float a2 = __expf(z2 - mz), a3 = __expf(z3 - mz);
            float inv = 1.f / (a0 + a1 + a2 + a3);
            a0 *= inv; a1 *= inv; a2 *= inv; a3 *= inv;
            float4 plo, phi;
            plo.x = a0*sv[0].x + a1*sv[1].x + a2*sv[2].x + a3*sv[3].x;
            plo.y = a0*sv[0].y + a1*sv[1].y + a2*sv[2].y + a3*sv[3].y;
            plo.z = a0*sv[0].z + a1*sv[1].z + a2*sv[2].z + a3*sv[3].z;
            plo.w = a0*sv[0].w + a1*sv[1].w + a2*sv[2].w + a3*sv[3].w;
            phi.x = a0*dv[0].x + a1*dv[1].x + a2*dv[2].x + a3*dv[3].x;
            phi.y = a0*dv[0].y + a1*dv[1].y + a2*dv[2].y + a3*dv[3].y;
            phi.z = a0*dv[0].z + a1*dv[1].z + a2*dv[2].z + a3*dv[3].z;
            phi.w = a0*dv[0].w + a1*dv[1].w + a2*dv[2].w + a3*dv[3].w;
            *(float4*)&sQK[el * QK_S + 4 * lane] = plo;         // in-place pooled
            *(float4*)&sQK[el * QK_S + 128 + 4 * lane] = phi;

            float4 eav = *(const float4*)&sEA[el * EA_S + 4 * lane];
            float4 kq0 = ((const float4*)g_kqg)[4 * lane + 0];
            float4 kq1 = ((const float4*)g_kqg)[4 * lane + 1];
            float4 kq2 = ((const float4*)g_kqg)[4 * lane + 2];
            float4 kq3 = ((const float4*)g_kqg)[4 * lane + 3];
            float g0 = eav.x*kq0.x + eav.y*kq1.x + eav.z*kq2.x + eav.w*kq3.x;
            float g1 = eav.x*kq0.y + eav.y*kq1.y + eav.z*kq2.y + eav.w*kq3.y;
            float g2 = eav.x*kq0.z + eav.y*kq1.z + eav.z*kq2.z + eav.w*kq3.z;
            float g3 = eav.x*kq0.w + eav.y*kq1.w + eav.z*kq2.w + eav.w*kq3.w;
            #pragma unroll
            for (int o = 16; o > 0; o >>= 1) {
                g0 += __shfl_xor_sync(0xFFFFFFFFu, g0, o);
                g1 += __shfl_xor_sync(0xFFFFFFFFu, g1, o);
                g2 += __shfl_xor_sync(0xFFFFFFFFu, g2, o);
                g3 += __shfl_xor_sync(0xFFFFFFFFu, g3, o);
            }
            float y0 = (g0 + g_cgs[0]) * SCALE, y1 = (g1 + g_cgs[1]) * SCALE;
            float y2 = (g2 + g_cgs[2]) * SCALE, y3 = (g3 + g_cgs[3]) * SCALE;
            float my = fmaxf(fmaxf(y0, y1), fmaxf(y2, y3));
            float b0 = __expf(y0 - my), b1 = __expf(y1 - my);
            float b2 = __expf(y2 - my), b3 = __expf(y3 - my);
            float binv = 1.f / (b0 + b1 + b2 + b3);
            b0 *= binv; b1 *= binv; b2 *= binv; b3 *= binv;
            if (lane == 0) {
                float* ap = attn_out + (size_t)eg * 4;
                ap[0] = b0; ap[1] = b1; ap[2] = b2; ap[3] = b3;
            }
            float4 m0v = ((const float4*)g_M)[lane];
            float4 m1v = ((const float4*)g_M)[32 + lane];
            float4 m2v = ((const float4*)g_M)[64 + lane];
            float4 m3v = ((const float4*)g_M)[96 + lane];
            float4 bo4 = ((const float4*)bo_g)[lane];
            float4 go;
            go.x = b0*m0v.x + b1*m1v.x + b2*m2v.x + b3*m3v.x + bo4.x;
            go.y = b0*m0v.y + b1*m1v.y + b2*m2v.y + b3*m3v.y + bo4.y;
            go.z = b0*m0v.z + b1*m1v.z + b2*m2v.z + b3*m3v.z + bo4.z;
            go.w = b0*m0v.w + b1*m1v.w + b2*m2v.w + b3*m3v.w + bo4.w;
            float* orow = out + (size_t)eg * 384;
            ((float4*)orow)[lane] = eav;
            ((float4*)(orow + 256))[lane] = go;
        }
    }
    __syncthreads();

    // ---- Phase C: local_out[64][128] = pooled[64][256] @ W2^T + bias2 ----
    // warps: 2m x 4n; warp tile m32 x n32; B direct from L2.
    {
        const int cm = wid >> 2;         // 0..1
        const int cn = wid & 3;          // 0..3
        const int m0 = cm * 32;
        const int n0 = cn * 32;
        float acc[2][4][4];
        #pragma unroll
        for (int am = 0; am < 2; ++am)
            #pragma unroll
            for (int bn = 0; bn < 4; ++bn)
                #pragma unroll
                for (int q = 0; q < 4; ++q) acc[am][bn][q] = 0.f;

        #pragma unroll 1
        for (int kb = 0; kb < 256; kb += 8) {
            uint2 bp[4];
            #pragma unroll
            for (int bn = 0; bn < 4; ++bn)
                bp[bn] = __ldg((const uint2*)&g_W2p[(n0 + 8 * bn + g) * 256 + kb + 2 * t4]);

            unsigned Ab[2][4], As[2][4];
            #pragma unroll
            for (int am = 0; am < 2; ++am) {
                int R = m0 + 16 * am;
                float a0 = sQK[(R + g)     * QK_S + kb + t4];
                float a1 = sQK[(R + g + 8) * QK_S + kb + t4];
                float a2 = sQK[(R + g)     * QK_S + kb + t4 + 4];
                float a3 = sQK[(R + g + 8) * QK_S + kb + t4 + 4];
                split_tf32(a0, Ab[am][0], As[am][0]);
                split_tf32(a1, Ab[am][1], As[am][1]);
                split_tf32(a2, Ab[am][2], As[am][2]);
                split_tf32(a3, Ab[am][3], As[am][3]);
            }
            #pragma unroll
            for (int bn = 0; bn < 4; ++bn) {
                unsigned b0b, b0s, b1b, b1s;
                split_tf32(__uint_as_float(bp[bn].x), b0b, b0s);
                split_tf32(__uint_as_float(bp[bn].y), b1b, b1s);
                #pragma unroll
                for (int am = 0; am < 2; ++am) {
                    mma8(acc[am][bn], As[am], b0b, b1b);
                    mma8(acc[am][bn], Ab[am], b0s, b1s);
                    mma8(acc[am][bn], Ab[am], b0b, b1b);
                }
            }
        }

        // epilogue: + bias2 -> out[:, 128:256]
        #pragma unroll
        for (int am = 0; am < 2; ++am) {
            #pragma unroll
            for (int bn = 0; bn < 4; ++bn) {
                int h = n0 + 8 * bn + 2 * t4;
                float2 bv = *(const float2*)&g_bias2[h];
                int e1 = e0 + m0 + 16 * am + g;
                if (e1 < E_TOT) {
                    *(float2*)&out[(size_t)e1 * 384 + 128 + h] =
                        make_float2(acc[am][bn][0] + bv.x, acc[am][bn][1] + bv.y);
                }
                int e2 = e1 + 8;
                if (e2 < E_TOT) {
                    *(float2*)&out[(size_t)e2 * 384 + 128 + h] =
                        make_float2(acc[am][bn][2] + bv.x, acc[am][bn][3] + bv.y);
                }
            }
        }
    }
}

// ---------------- launch ---------------------------------------------------
extern "C" void kernel_launch(void* const* d_in, const int* in_sizes, int n_in,
                              void* d_out, int out_size) {
    const float* ea   = (const float*)d_in[0];
    const float* gf   = (const float*)d_in[1];
    const int*   ei   = (const int*)d_in[2];
    const float* wq_l = (const float*)d_in[3];
    const float* wk_l = (const float*)d_in[4];
    const float* wv_l = (const float*)d_in[5];
    const float* bq_l = (const float*)d_in[6];
    const float* bv_l = (const float*)d_in[8];
    const float* wo_l = (const float*)d_in[9];
    const float* bo_l = (const float*)d_in[10];
    const float* wq_g = (const float*)d_in[11];
    const float* wk_g = (const float*)d_in[12];
    const float* wv_g = (const float*)d_in[13];
    const float* bq_g = (const float*)d_in[14];
    const float* bk_g = (const float*)d_in[15];
    const float* bv_g = (const float*)d_in[16];
    const float* wo_g = (const float*)d_in[17];
    const float* bo_g = (const float*)d_in[18];

    float* out        = (float*)d_out;
    float* out_pooled = out + (size_t)E_TOT * 384;
    float* out_attn   = out_pooled + 512;

    const int MAIN_SMEM = (8448 + 16640) * 4;   // 100352 B

    cudaFuncSetAttribute(k1_precompute,
                         cudaFuncAttributeMaxDynamicSharedMemorySize, 67584);
    cudaFuncSetAttribute(k2_small,
                         cudaFuncAttributeMaxDynamicSharedMemorySize, 67584);
    cudaFuncSetAttribute(main_edge_kernel,
                         cudaFuncAttributeMaxDynamicSharedMemorySize, MAIN_SMEM);

    k1_precompute<<<586, 512, 67584>>>(gf, wq_l, wk_l, wv_l, wo_l,
                                       bq_l, bv_l, bo_l);
    k2_small<<<1, 512, 67584>>>(wk_g, wv_g, wo_g, wq_g,
                                bk_g, bv_g, bq_g, out_pooled);
    main_edge_kernel<<<GRID_MAIN, 256, MAIN_SMEM>>>(ea, gf, ei, bo_g, out, out_attn);
}

// round 7
// speedup vs baseline: 2.7918x; 1.2132x over previous
#include <cuda_runtime.h>
#include <cuda_bf16.h>

#define E_TOT   100000
#define NN      50000
#define POOL_BLKS 200
#define ROWS_PER_BLK 250
#define TILE_E  64
#define GRID_MAIN ((E_TOT + TILE_E - 1) / TILE_E)
#define EA_U    68      /* sEAhi/sEAlo row stride in uints (64 data + 4 pad) */
#define QK_S    260     /* sQK row stride (floats) */
#define SCALE   0.08838834764831845f   /* 1/sqrt(128) */

// ---------------- device scratch ----------------
__device__ float g_partial[POOL_BLKS * 512];
__device__ float g_pooled[512];
__device__ float g_kg[512];
__device__ float g_vg[512];
__device__ float g_M[512];          // [4][128] = v_g @ wo_g^T
__device__ float g_kqg[512];        // [128][4]
__device__ float g_cgs[4];
__device__ float g_c0[256];         // bq_l @ wk_l
__device__ float g_bias2[128];      // bv_l @ wo_l^T + bo_l
// B matrices pre-split to bf16 hi/lo in m16n8k16 fragment order:
// uint4 per (n, kg, t4) = {hi_k(2t4,2t4+1), hi_k(+8,+9), lo_k01, lo_k89}
__device__ uint4 g_Cb4[256 * 8 * 4];    // C:  n=256, k=128 (kg 0..7)
__device__ uint4 g_W2b4[128 * 16 * 4];  // W2: n=128, k=256 (kg 0..15)

__device__ __forceinline__ float dot4(float4 a, float4 b) {
    return a.x * b.x + a.y * b.y + a.z * b.z + a.w * b.w;
}

__device__ __forceinline__ void mma16(float* d, const unsigned* a, unsigned b0, unsigned b1) {
    asm volatile(
        "mma.sync.aligned.m16n8k16.row.col.f32.bf16.bf16.f32 "
        "{%0,%1,%2,%3}, {%4,%5,%6,%7}, {%8,%9}, {%0,%1,%2,%3};"
        : "+f"(d[0]), "+f"(d[1]), "+f"(d[2]), "+f"(d[3])
        : "r"(a[0]), "r"(a[1]), "r"(a[2]), "r"(a[3]), "r"(b0), "r"(b1));
}

__device__ __forceinline__ unsigned bf2_as_u(__nv_bfloat162 h) {
    return *(unsigned*)&h;
}
__device__ __forceinline__ __nv_bfloat162 u_as_bf2(unsigned u) {
    return *(__nv_bfloat162*)&u;
}

// split float pair -> hi bf16x2, lo bf16x2
__device__ __forceinline__ void split_bf2(float x, float y, unsigned& hi, unsigned& lo) {
    __nv_bfloat162 h = __float22bfloat162_rn(make_float2(x, y));
    float2 hf = __bfloat1622float2(h);
    __nv_bfloat162 l = __float22bfloat162_rn(make_float2(x - hf.x, y - hf.y));
    hi = bf2_as_u(h);
    lo = bf2_as_u(l);
}

// write one fp32 value as pre-split bf16 hi/lo into fragment-ordered array.
// base: bf16* view of g_Cb4 / g_W2b4; n = output col; k = reduction index;
// kgs = number of uint4 groups per n (8 for C, 16 for W2)
__device__ __forceinline__ void write_b_split(__nv_bfloat16* base, int n, int k,
                                              int kgs, float v) {
    int kg = k >> 4, r = k & 15;
    int word, t4;
    if (r < 8) { t4 = r >> 1; word = 0; }
    else       { t4 = (r - 8) >> 1; word = 1; }
    int half = r & 1;
    size_t bidx = ((((size_t)(n * kgs + kg) * 4 + t4) * 4 + word) * 2 + half);
    __nv_bfloat16 hi = __float2bfloat16(v);
    __nv_bfloat16 lo = __float2bfloat16(v - __bfloat162float(hi));
    base[bidx] = hi;
    base[bidx + 4] = lo;   // lo word = word+2 -> +4 bf16 elements
}

// ---------------- kernel 1: pool partials + C + W2 + c0 + bias2 ----------
// blocks 0..199: pool partial; 200..327: C k-rows; 328..583: W2 k-rows;
// 584: c0; 585: bias2.  512 threads each.
__global__ void k1_precompute(const float* __restrict__ gf,
                              const float* __restrict__ wq_l,
                              const float* __restrict__ wk_l,
                              const float* __restrict__ wv_l,
                              const float* __restrict__ wo_l,
                              const float* __restrict__ bq_l,
                              const float* __restrict__ bv_l,
                              const float* __restrict__ bo_l) {
    extern __shared__ float st[];
    int b = blockIdx.x, t = threadIdx.x;
    if (b < POOL_BLKS) {
        const float* p = gf + (size_t)b * ROWS_PER_BLK * 512 + t;
        float s = 0.f;
        #pragma unroll 5
        for (int r = 0; r < ROWS_PER_BLK; ++r) s += p[(size_t)r * 512];
        g_partial[b * 512 + t] = s;
    } else if (b < 328) {
        int i = b - 200;            // C k-row 0..127
        if (t < 256) {
            float a = 0.f;
            for (int h = 0; h < 128; ++h)
                a += __ldg(&wq_l[h * 128 + i]) * wk_l[h * 256 + t];
            write_b_split((__nv_bfloat16*)g_Cb4, t, i, 8, a);
        }
    } else if (b < 584) {
        int j = b - 328;            // W2 k-index 0..255
        for (int idx = t; idx < 16384; idx += 512) {
            int h = idx >> 7, m = idx & 127;
            st[m * 132 + h] = wo_l[idx];
        }
        __syncthreads();
        if (t < 128) {
            float a = 0.f;
            for (int m = 0; m < 128; ++m)
                a += __ldg(&wv_l[m * 256 + j]) * st[m * 132 + t];
            write_b_split((__nv_bfloat16*)g_W2b4, t, j, 16, a);
        }
    } else if (b == 584) {
        if (t < 256) {
            float a = 0.f;
            for (int h = 0; h < 128; ++h) a += bq_l[h] * wk_l[h * 256 + t];
            g_c0[t] = a;
        }
    } else {
        for (int idx = t; idx < 16384; idx += 512) {
            int h = idx >> 7, m = idx & 127;
            st[m * 132 + h] = wo_l[idx];
        }
        __syncthreads();
        if (t < 128) {
            float a = 0.f;
            for (int m = 0; m < 128; ++m) a += bv_l[m] * st[m * 132 + t];
            g_bias2[t] = a + bo_l[t];
        }
    }
}

// ---------------- kernel 2: pooled + global-path small matrices ----------
__global__ void k2_small(const float* __restrict__ wk_g,
                         const float* __restrict__ wv_g,
                         const float* __restrict__ wo_g,
                         const float* __restrict__ wq_g,
                         const float* __restrict__ bk_g,
                         const float* __restrict__ bv_g,
                         const float* __restrict__ bq_g,
                         float* __restrict__ out_pooled) {
    extern __shared__ float st[];
    int t = threadIdx.x;

    float s = 0.f;
    for (int b = 0; b < POOL_BLKS; ++b) s += g_partial[b * 512 + t];
    s *= (1.0f / NN);
    g_pooled[t] = s;
    out_pooled[t] = s;
    __syncthreads();

    for (int idx = t; idx < 16384; idx += 512) {
        int h = idx >> 7, j = idx & 127; st[j * 132 + h] = wk_g[idx];
    }
    __syncthreads();
    {
        int si = t >> 7, h = t & 127; float a = 0.f;
        for (int j = 0; j < 128; ++j) a += g_pooled[si * 128 + j] * st[j * 132 + h];
        g_kg[t] = a + bk_g[h];
    }
    __syncthreads();

    for (int idx = t; idx < 16384; idx += 512) {
        int h = idx >> 7, j = idx & 127; st[j * 132 + h] = wv_g[idx];
    }
    __syncthreads();
    {
        int si = t >> 7, h = t & 127; float a = 0.f;
        for (int j = 0; j < 128; ++j) a += g_pooled[si * 128 + j] * st[j * 132 + h];
        g_vg[t] = a + bv_g[h];
    }
    __syncthreads();

    for (int idx = t; idx < 16384; idx += 512) {
        int h = idx >> 7, m = idx & 127; st[m * 132 + h] = wo_g[idx];
    }
    __syncthreads();
    {
        int si = t >> 7, h = t & 127; float a = 0.f;
        for (int m = 0; m < 128; ++m) a += g_vg[si * 128 + m] * st[m * 132 + h];
        g_M[t] = a;
    }
    __syncthreads();

    for (int idx = t; idx < 16384; idx += 512) {
        int h = idx >> 7, i = idx & 127; st[i * 132 + h] = wq_g[idx];
    }
    __syncthreads();
    {
        int i = t >> 2, si = t & 3; float a = 0.f;
        for (int h = 0; h < 128; ++h) a += st[i * 132 + h] * g_kg[si * 128 + h];
        g_kqg[i * 4 + si] = a;
    }
    if (t < 4) {
        float a = 0.f;
        for (int h = 0; h < 128; ++h) a += bq_g[h] * g_kg[t * 128 + h];
        g_cgs[t] = a;
    }
}

// ---------------- kernel 3: fused per-edge kernel (256 thr, 2 CTA/SM) ----
__global__ void __launch_bounds__(256, 2)
main_edge_kernel(const float* __restrict__ ea_g,
                 const float* __restrict__ gf,
                 const int* __restrict__ ei,
                 const float* __restrict__ bo_g,
                 float* __restrict__ out,
                 float* __restrict__ attn_out) {
    extern __shared__ float smem[];
    unsigned* sEAhi = (unsigned*)smem;            // 64*68 uints
    unsigned* sEAlo = sEAhi + 64 * EA_U;          // 64*68 uints
    float*    sQK   = smem + 2 * 64 * EA_U;       // 64*260 floats
    const int tid  = threadIdx.x;
    const int wid  = tid >> 5;    // 0..7
    const int lane = tid & 31;
    const int g    = lane >> 2;   // 0..7
    const int t4   = lane & 3;    // 0..3
    const int e0   = blockIdx.x * TILE_E;

    // stage edge_attr tile pre-split to bf16 hi/lo (zero-fill OOB rows)
    for (int idx = tid; idx < 2048; idx += 256) {
        int r = idx >> 5, c = idx & 31;          // c: float4 col (k = 4c)
        float4 v = make_float4(0.f, 0.f, 0.f, 0.f);
        if (e0 + r < E_TOT) v = ((const float4*)ea_g)[(size_t)(e0 + r) * 32 + c];
        unsigned h0, l0, h1, l1;
        split_bf2(v.x, v.y, h0, l0);
        split_bf2(v.z, v.w, h1, l1);
        sEAhi[r * EA_U + 2 * c]     = h0;
        sEAhi[r * EA_U + 2 * c + 1] = h1;
        sEAlo[r * EA_U + 2 * c]     = l0;
        sEAlo[r * EA_U + 2 * c + 1] = l1;
    }
    __syncthreads();

    // ---- Phase A: qk[64][256] = ea @ C + c0 (bf16 m16n8k16, 3-term) ----
    // warps: 2m x 4n; warp tile m32 x n64; B direct from L2 (pre-split).
    {
        const int wm = wid >> 2;          // 0..1
        const int wn = wid & 3;           // 0..3
        const int m0 = wm * 32;
        const int n0 = wn * 64;
        float acc[2][8][4];
        #pragma unroll
        for (int am = 0; am < 2; ++am)
            #pragma unroll
            for (int bn = 0; bn < 8; ++bn)
                #pragma unroll
                for (int q = 0; q < 4; ++q) acc[am][bn][q] = 0.f;

        #pragma unroll 1
        for (int kg = 0; kg < 8; ++kg) {
            unsigned Ah[2][4], Al[2][4];
            #pragma unroll
            for (int am = 0; am < 2; ++am) {
                int R = m0 + 16 * am;
                Ah[am][0] = sEAhi[(R + g)     * EA_U + kg * 8 + t4];
                Ah[am][1] = sEAhi[(R + g + 8) * EA_U + kg * 8 + t4];
                Ah[am][2] = sEAhi[(R + g)     * EA_U + kg * 8 + 4 + t4];
                Ah[am][3] = sEAhi[(R + g + 8) * EA_U + kg * 8 + 4 + t4];
                Al[am][0] = sEAlo[(R + g)     * EA_U + kg * 8 + t4];
                Al[am][1] = sEAlo[(R + g + 8) * EA_U + kg * 8 + t4];
                Al[am][2] = sEAlo[(R + g)     * EA_U + kg * 8 + 4 + t4];
                Al[am][3] = sEAlo[(R + g + 8) * EA_U + kg * 8 + 4 + t4];
            }
            #pragma unroll
            for (int hh = 0; hh < 2; ++hh) {
                uint4 bp[4];
                #pragma unroll
                for (int b2 = 0; b2 < 4; ++b2)
                    bp[b2] = __ldg(&g_Cb4[((n0 + 32 * hh + 8 * b2 + g) * 8 + kg) * 4 + t4]);
                #pragma unroll
                for (int b2 = 0; b2 < 4; ++b2) {
                    int bn = 4 * hh + b2;
                    #pragma unroll
                    for (int am = 0; am < 2; ++am) {
                        mma16(acc[am][bn], Ah[am], bp[b2].x, bp[b2].y);
                        mma16(acc[am][bn], Ah[am], bp[b2].z, bp[b2].w);
                        mma16(acc[am][bn], Al[am], bp[b2].x, bp[b2].y);
                    }
                }
            }
        }

        // epilogue: qk + c0 -> sQK
        #pragma unroll
        for (int am = 0; am < 2; ++am) {
            #pragma unroll
            for (int bn = 0; bn < 8; ++bn) {
                int col = n0 + 8 * bn + 2 * t4;
                float2 c0v = *(const float2*)&g_c0[col];
                int r1 = m0 + 16 * am + g;
                *(float2*)&sQK[r1 * QK_S + col] =
                    make_float2(acc[am][bn][0] + c0v.x, acc[am][bn][1] + c0v.y);
                *(float2*)&sQK[(r1 + 8) * QK_S + col] =
                    make_float2(acc[am][bn][2] + c0v.x, acc[am][bn][3] + c0v.y);
            }
        }
    }
    __syncthreads();

    // ---- Phase B: gather + local softmax + pooled feats + global path ----
    #pragma unroll 1
    for (int r = 0; r < 8; ++r) {
        int el = 8 * wid + r;
        int eg = e0 + el;
        if (eg < E_TOT) {
            int i0 = ei[eg];
            int i1 = ei[E_TOT + eg];
            const float4* srcp = (const float4*)(gf + (size_t)i0 * 512);
            const float4* dstp = (const float4*)(gf + (size_t)i1 * 512);
            float4 sv[4], dv[4];
            #pragma unroll
            for (int s2 = 0; s2 < 4; ++s2) {
                sv[s2] = srcp[s2 * 32 + lane];
                dv[s2] = dstp[s2 * 32 + lane];
            }
            float4 qlo = *(const float4*)&sQK[el * QK_S + 4 * lane];
            float4 qhi = *(const float4*)&sQK[el * QK_S + 128 + 4 * lane];
            float sc0 = dot4(qlo, sv[0]) + dot4(qhi, dv[0]);
            float sc1 = dot4(qlo, sv[1]) + dot4(qhi, dv[1]);
            float sc2 = dot4(qlo, sv[2]) + dot4(qhi, dv[2]);
            float sc3 = dot4(qlo, sv[3]) + dot4(qhi, dv[3]);
            #pragma unroll
            for (int o = 16; o > 0; o >>= 1) {
                sc0 += __shfl_xor_sync(0xFFFFFFFFu, sc0, o);
                sc1 += __shfl_xor_sync(0xFFFFFFFFu, sc1, o);
                sc2 += __shfl_xor_sync(0xFFFFFFFFu, sc2, o);
                sc3 += __shfl_xor_sync(0xFFFFFFFFu, sc3, o);
            }
            float z0 = sc0 * SCALE, z1 = sc1 * SCALE, z2 = sc2 * SCALE, z3 = sc3 * SCALE;
            float mz = fmaxf(fmaxf(z0, z1), fmaxf(z2, z3));
            float a0 = __expf(z0 - mz), a1 = __expf(z1 - mz);
            float a2 = __expf(z2 - mz), a3 = __expf(z3 - mz);
            float inv = 1.f / (a0 + a1 + a2 + a3);
            a0 *= inv; a1 *= inv; a2 *= inv; a3 *= inv;
            float4 plo, phi;
            plo.x = a0*sv[0].x + a1*sv[1].x + a2*sv[2].x + a3*sv[3].x;
            plo.y = a0*sv[0].y + a1*sv[1].y + a2*sv[2].y + a3*sv[3].y;
            plo.z = a0*sv[0].z + a1*sv[1].z + a2*sv[2].z + a3*sv[3].z;
            plo.w = a0*sv[0].w + a1*sv[1].w + a2*sv[2].w + a3*sv[3].w;
            phi.x = a0*dv[0].x + a1*dv[1].x + a2*dv[2].x + a3*dv[3].x;
            phi.y = a0*dv[0].y + a1*dv[1].y + a2*dv[2].y + a3*dv[3].y;
            phi.z = a0*dv[0].z + a1*dv[1].z + a2*dv[2].z + a3*dv[3].z;
            phi.w = a0*dv[0].w + a1*dv[1].w + a2*dv[2].w + a3*dv[3].w;
            *(float4*)&sQK[el * QK_S + 4 * lane] = plo;         // in-place pooled
            *(float4*)&sQK[el * QK_S + 128 + 4 * lane] = phi;

            // reconstruct edge_attr from hi+lo (error ~ 8e-6 relative)
            unsigned hu0 = sEAhi[el * EA_U + 2 * lane];
            unsigned hu1 = sEAhi[el * EA_U + 2 * lane + 1];
            unsigned lu0 = sEAlo[el * EA_U + 2 * lane];
            unsigned lu1 = sEAlo[el * EA_U + 2 * lane + 1];
            float2 hf0 = __bfloat1622float2(u_as_bf2(hu0));
            float2 hf1 = __bfloat1622float2(u_as_bf2(hu1));
            float2 lf0 = __bfloat1622float2(u_as_bf2(lu0));
            float2 lf1 = __bfloat1622float2(u_as_bf2(lu1));
            float4 eav = make_float4(hf0.x + lf0.x, hf0.y + lf0.y,
                                     hf1.x + lf1.x, hf1.y + lf1.y);

            float4 kq0 = ((const float4*)g_kqg)[4 * lane + 0];
            float4 kq1 = ((const float4*)g_kqg)[4 * lane + 1];
            float4 kq2 = ((const float4*)g_kqg)[4 * lane + 2];
            float4 kq3 = ((const float4*)g_kqg)[4 * lane + 3];
            float g0 = eav.x*kq0.x + eav.y*kq1.x + eav.z*kq2.x + eav.w*kq3.x;
            float g1 = eav.x*kq0.y + eav.y*kq1.y + eav.z*kq2.y + eav.w*kq3.y;
            float g2 = eav.x*kq0.z + eav.y*kq1.z + eav.z*kq2.z + eav.w*kq3.z;
            float g3 = eav.x*kq0.w + eav.y*kq1.w + eav.z*kq2.w + eav.w*kq3.w;
            #pragma unroll
            for (int o = 16; o > 0; o >>= 1) {
                g0 += __shfl_xor_sync(0xFFFFFFFFu, g0, o);
                g1 += __shfl_xor_sync(0xFFFFFFFFu, g1, o);
                g2 += __shfl_xor_sync(0xFFFFFFFFu, g2, o);
                g3 += __shfl_xor_sync(0xFFFFFFFFu, g3, o);
            }
            float y0 = (g0 + g_cgs[0]) * SCALE, y1 = (g1 + g_cgs[1]) * SCALE;
            float y2 = (g2 + g_cgs[2]) * SCALE, y3 = (g3 + g_cgs[3]) * SCALE;
            float my = fmaxf(fmaxf(y0, y1), fmaxf(y2, y3));
            float b0 = __expf(y0 - my), b1 = __expf(y1 - my);
            float b2 = __expf(y2 - my), b3 = __expf(y3 - my);
            float binv = 1.f / (b0 + b1 + b2 + b3);
            b0 *= binv; b1 *= binv; b2 *= binv; b3 *= binv;
            if (lane == 0) {
                float* ap = attn_out + (size_t)eg * 4;
                ap[0] = b0; ap[1] = b1; ap[2] = b2; ap[3] = b3;
            }
            float4 m0v = ((const float4*)g_M)[lane];
            float4 m1v = ((const float4*)g_M)[32 + lane];
            float4 m2v = ((const float4*)g_M)[64 + lane];
            float4 m3v = ((const float4*)g_M)[96 + lane];
            float4 bo4 = ((const float4*)bo_g)[lane];
            float4 go;
            go.x = b0*m0v.x + b1*m1v.x + b2*m2v.x + b3*m3v.x + bo4.x;
            go.y = b0*m0v.y + b1*m1v.y + b2*m2v.y + b3*m3v.y + bo4.y;
            go.z = b0*m0v.z + b1*m1v.z + b2*m2v.z + b3*m3v.z + bo4.z;
            go.w = b0*m0v.w + b1*m1v.w + b2*m2v.w + b3*m3v.w + bo4.w;
            float* orow = out + (size_t)eg * 384;
            ((float4*)orow)[lane] = eav;
            ((float4*)(orow + 256))[lane] = go;
        }
    }
    __syncthreads();

    // ---- Phase C: local_out[64][128] = pooled @ W2^T + bias2 (bf16) ----
    // warps: 2m x 4n; warp tile m32 x n32.
    {
        const int cm = wid >> 2;         // 0..1
        const int cn = wid & 3;          // 0..3
        const int m0 = cm * 32;
        const int n0 = cn * 32;
        float acc[2][4][4];
        #pragma unroll
        for (int am = 0; am < 2; ++am)
            #pragma unroll
            for (int bn = 0; bn < 4; ++bn)
                #pragma unroll
                for (int q = 0; q < 4; ++q) acc[am][bn][q] = 0.f;

        #pragma unroll 1
        for (int kg = 0; kg < 16; ++kg) {
            uint4 bp[4];
            #pragma unroll
            for (int bn = 0; bn < 4; ++bn)
                bp[bn] = __ldg(&g_W2b4[((n0 + 8 * bn + g) * 16 + kg) * 4 + t4]);

            unsigned Ah[2][4], Al[2][4];
            #pragma unroll
            for (int am = 0; am < 2; ++am) {
                int R = m0 + 16 * am;
                float2 p00 = *(const float2*)&sQK[(R + g)     * QK_S + kg * 16 + 2 * t4];
                float2 p10 = *(const float2*)&sQK[(R + g + 8) * QK_S + kg * 16 + 2 * t4];
                float2 p01 = *(const float2*)&sQK[(R + g)     * QK_S + kg * 16 + 2 * t4 + 8];
                float2 p11 = *(const float2*)&sQK[(R + g + 8) * QK_S + kg * 16 + 2 * t4 + 8];
                split_bf2(p00.x, p00.y, Ah[am][0], Al[am][0]);
                split_bf2(p10.x, p10.y, Ah[am][1], Al[am][1]);
                split_bf2(p01.x, p01.y, Ah[am][2], Al[am][2]);
                split_bf2(p11.x, p11.y, Ah[am][3], Al[am][3]);
            }
            #pragma unroll
            for (int bn = 0; bn < 4; ++bn) {
                #pragma unroll
                for (int am = 0; am < 2; ++am) {
                    mma16(acc[am][bn], Ah[am], bp[bn].x, bp[bn].y);
                    mma16(acc[am][bn], Ah[am], bp[bn].z, bp[bn].w);
                    mma16(acc[am][bn], Al[am], bp[bn].x, bp[bn].y);
                }
            }
        }

        // epilogue: + bias2 -> out[:, 128:256]
        #pragma unroll
        for (int am = 0; am < 2; ++am) {
            #pragma unroll
            for (int bn = 0; bn < 4; ++bn) {
                int h = n0 + 8 * bn + 2 * t4;
                float2 bv = *(const float2*)&g_bias2[h];
                int e1 = e0 + m0 + 16 * am + g;
                if (e1 < E_TOT) {
                    *(float2*)&out[(size_t)e1 * 384 + 128 + h] =
                        make_float2(acc[am][bn][0] + bv.x, acc[am][bn][1] + bv.y);
                }
                int e2 = e1 + 8;
                if (e2 < E_TOT) {
                    *(float2*)&out[(size_t)e2 * 384 + 128 + h] =
                        make_float2(acc[am][bn][2] + bv.x, acc[am][bn][3] + bv.y);
                }
            }
        }
    }
}

// ---------------- launch ---------------------------------------------------
extern "C" void kernel_launch(void* const* d_in, const int* in_sizes, int n_in,
                              void* d_out, int out_size) {
    const float* ea   = (const float*)d_in[0];
    const float* gf   = (const float*)d_in[1];
    const int*   ei   = (const int*)d_in[2];
    const float* wq_l = (const float*)d_in[3];
    const float* wk_l = (const float*)d_in[4];
    const float* wv_l = (const float*)d_in[5];
    const float* bq_l = (const float*)d_in[6];
    const float* bv_l = (const float*)d_in[8];
    const float* wo_l = (const float*)d_in[9];
    const float* bo_l = (const float*)d_in[10];
    const float* wq_g = (const float*)d_in[11];
    const float* wk_g = (const float*)d_in[12];
    const float* wv_g = (const float*)d_in[13];
    const float* bq_g = (const float*)d_in[14];
    const float* bk_g = (const float*)d_in[15];
    const float* bv_g = (const float*)d_in[16];
    const float* wo_g = (const float*)d_in[17];
    const float* bo_g = (const float*)d_in[18];

    float* out        = (float*)d_out;
    float* out_pooled = out + (size_t)E_TOT * 384;
    float* out_attn   = out_pooled + 512;

    const int MAIN_SMEM = (2 * 64 * EA_U + 16640) * 4;   // 101376 B

    cudaFuncSetAttribute(k1_precompute,
                         cudaFuncAttributeMaxDynamicSharedMemorySize, 67584);
    cudaFuncSetAttribute(k2_small,
                         cudaFuncAttributeMaxDynamicSharedMemorySize, 67584);
    cudaFuncSetAttribute(main_edge_kernel,
                         cudaFuncAttributeMaxDynamicSharedMemorySize, MAIN_SMEM);

    k1_precompute<<<586, 512, 67584>>>(gf, wq_l, wk_l, wv_l, wo_l,
                                       bq_l, bv_l, bo_l);
    k2_small<<<1, 512, 67584>>>(wk_g, wv_g, wo_g, wq_g,
                                bk_g, bv_g, bq_g, out_pooled);
    main_edge_kernel<<<GRID_MAIN, 256, MAIN_SMEM>>>(ea, gf, ei, bo_g, out, out_attn);
}

// round 8
// speedup vs baseline: 2.8508x; 1.0211x over previous
#include <cuda_runtime.h>
#include <cuda_bf16.h>

#define E_TOT   100000
#define NN      50000
#define POOL_BLKS 592
#define ROWS_PER_BLK 85
#define TILE_E  64
#define GRID_MAIN ((E_TOT + TILE_E - 1) / TILE_E)
#define EA_U    68      /* sEAhi/sEAlo row stride in uints (64 data + 4 pad) */
#define QK_S    260     /* sQK row stride (floats) */
#define SCALE   0.08838834764831845f   /* 1/sqrt(128) */

// ---------------- device scratch ----------------
__device__ float g_partial[POOL_BLKS * 512];
__device__ float g_pooled[512];
__device__ float g_kg[512];
__device__ float g_vg[512];
__device__ float g_M[512];          // [4][128] = v_g @ wo_g^T
__device__ float g_kqg[512];        // [128][4]
__device__ float g_cgs[4];
__device__ float g_c0[256];         // bq_l @ wk_l
__device__ float g_bias2[128];      // bv_l @ wo_l^T + bo_l
// B matrices pre-split to bf16 hi/lo in m16n8k16 fragment order:
// uint4 per (n, kg, t4) = {hi_k(2t4,2t4+1), hi_k(+8,+9), lo_k01, lo_k89}
__device__ uint4 g_Cb4[256 * 8 * 4];    // C:  n=256, k=128 (kg 0..7)
__device__ uint4 g_W2b4[128 * 16 * 4];  // W2: n=128, k=256 (kg 0..15)

__device__ __forceinline__ float dot4(float4 a, float4 b) {
    return a.x * b.x + a.y * b.y + a.z * b.z + a.w * b.w;
}

__device__ __forceinline__ void mma16(float* d, const unsigned* a, unsigned b0, unsigned b1) {
    asm volatile(
        "mma.sync.aligned.m16n8k16.row.col.f32.bf16.bf16.f32 "
        "{%0,%1,%2,%3}, {%4,%5,%6,%7}, {%8,%9}, {%0,%1,%2,%3};"
        : "+f"(d[0]), "+f"(d[1]), "+f"(d[2]), "+f"(d[3])
        : "r"(a[0]), "r"(a[1]), "r"(a[2]), "r"(a[3]), "r"(b0), "r"(b1));
}

__device__ __forceinline__ unsigned bf2_as_u(__nv_bfloat162 h) {
    return *(unsigned*)&h;
}
__device__ __forceinline__ __nv_bfloat162 u_as_bf2(unsigned u) {
    return *(__nv_bfloat162*)&u;
}

// split float pair -> hi bf16x2, lo bf16x2
__device__ __forceinline__ void split_bf2(float x, float y, unsigned& hi, unsigned& lo) {
    __nv_bfloat162 h = __float22bfloat162_rn(make_float2(x, y));
    float2 hf = __bfloat1622float2(h);
    __nv_bfloat162 l = __float22bfloat162_rn(make_float2(x - hf.x, y - hf.y));
    hi = bf2_as_u(h);
    lo = bf2_as_u(l);
}

// write one fp32 value as pre-split bf16 hi/lo into fragment-ordered array.
__device__ __forceinline__ void write_b_split(__nv_bfloat16* base, int n, int k,
                                              int kgs, float v) {
    int kg = k >> 4, r = k & 15;
    int word, t4;
    if (r < 8) { t4 = r >> 1; word = 0; }
    else       { t4 = (r - 8) >> 1; word = 1; }
    int half = r & 1;
    size_t bidx = ((((size_t)(n * kgs + kg) * 4 + t4) * 4 + word) * 2 + half);
    __nv_bfloat16 hi = __float2bfloat16(v);
    __nv_bfloat16 lo = __float2bfloat16(v - __bfloat162float(hi));
    base[bidx] = hi;
    base[bidx + 4] = lo;
}

// ---------------- kernel 1: pool partials + C + W2 + c0 + bias2 ----------
// blocks 0..591: pool partial; 592..719: C k-rows; 720..975: W2 k-rows;
// 976: c0; 977: bias2.  512 threads each.
__global__ void k1_precompute(const float* __restrict__ gf,
                              const float* __restrict__ wq_l,
                              const float* __restrict__ wk_l,
                              const float* __restrict__ wv_l,
                              const float* __restrict__ wo_l,
                              const float* __restrict__ bq_l,
                              const float* __restrict__ bv_l,
                              const float* __restrict__ bo_l) {
    extern __shared__ float st[];
    int b = blockIdx.x, t = threadIdx.x;
    if (b < POOL_BLKS) {
        int r0 = b * ROWS_PER_BLK;
        const float* p = gf + (size_t)r0 * 512 + t;
        float s = 0.f;
        #pragma unroll 5
        for (int r = 0; r < ROWS_PER_BLK; ++r)
            if (r0 + r < NN) s += p[(size_t)r * 512];
        g_partial[b * 512 + t] = s;
    } else if (b < POOL_BLKS + 128) {
        int i = b - POOL_BLKS;      // C k-row 0..127
        if (t < 256) {
            float a = 0.f;
            for (int h = 0; h < 128; ++h)
                a += __ldg(&wq_l[h * 128 + i]) * wk_l[h * 256 + t];
            write_b_split((__nv_bfloat16*)g_Cb4, t, i, 8, a);
        }
    } else if (b < POOL_BLKS + 384) {
        int j = b - (POOL_BLKS + 128);   // W2 k-index 0..255
        for (int idx = t; idx < 16384; idx += 512) {
            int h = idx >> 7, m = idx & 127;
            st[m * 132 + h] = wo_l[idx];
        }
        __syncthreads();
        if (t < 128) {
            float a = 0.f;
            for (int m = 0; m < 128; ++m)
                a += __ldg(&wv_l[m * 256 + j]) * st[m * 132 + t];
            write_b_split((__nv_bfloat16*)g_W2b4, t, j, 16, a);
        }
    } else if (b == POOL_BLKS + 384) {
        if (t < 256) {
            float a = 0.f;
            for (int h = 0; h < 128; ++h) a += bq_l[h] * wk_l[h * 256 + t];
            g_c0[t] = a;
        }
    } else {
        for (int idx = t; idx < 16384; idx += 512) {
            int h = idx >> 7, m = idx & 127;
            st[m * 132 + h] = wo_l[idx];
        }
        __syncthreads();
        if (t < 128) {
            float a = 0.f;
            for (int m = 0; m < 128; ++m) a += bv_l[m] * st[m * 132 + t];
            g_bias2[t] = a + bo_l[t];
        }
    }
}

// ---------------- kernel 2: pooled + global-path small matrices ----------
__global__ void k2_small(const float* __restrict__ wk_g,
                         const float* __restrict__ wv_g,
                         const float* __restrict__ wo_g,
                         const float* __restrict__ wq_g,
                         const float* __restrict__ bk_g,
                         const float* __restrict__ bv_g,
                         const float* __restrict__ bq_g,
                         float* __restrict__ out_pooled) {
    extern __shared__ float st[];
    int t = threadIdx.x;

    float s = 0.f;
    for (int b = 0; b < POOL_BLKS; ++b) s += g_partial[b * 512 + t];
    s *= (1.0f / NN);
    g_pooled[t] = s;
    out_pooled[t] = s;
    __syncthreads();

    for (int idx = t; idx < 16384; idx += 512) {
        int h = idx >> 7, j = idx & 127; st[j * 132 + h] = wk_g[idx];
    }
    __syncthreads();
    {
        int si = t >> 7, h = t & 127; float a = 0.f;
        for (int j = 0; j < 128; ++j) a += g_pooled[si * 128 + j] * st[j * 132 + h];
        g_kg[t] = a + bk_g[h];
    }
    __syncthreads();

    for (int idx = t; idx < 16384; idx += 512) {
        int h = idx >> 7, j = idx & 127; st[j * 132 + h] = wv_g[idx];
    }
    __syncthreads();
    {
        int si = t >> 7, h = t & 127; float a = 0.f;
        for (int j = 0; j < 128; ++j) a += g_pooled[si * 128 + j] * st[j * 132 + h];
        g_vg[t] = a + bv_g[h];
    }
    __syncthreads();

    for (int idx = t; idx < 16384; idx += 512) {
        int h = idx >> 7, m = idx & 127; st[m * 132 + h] = wo_g[idx];
    }
    __syncthreads();
    {
        int si = t >> 7, h = t & 127; float a = 0.f;
        for (int m = 0; m < 128; ++m) a += g_vg[si * 128 + m] * st[m * 132 + h];
        g_M[t] = a;
    }
    __syncthreads();

    for (int idx = t; idx < 16384; idx += 512) {
        int h = idx >> 7, i = idx & 127; st[i * 132 + h] = wq_g[idx];
    }
    __syncthreads();
    {
        int i = t >> 2, si = t & 3; float a = 0.f;
        for (int h = 0; h < 128; ++h) a += st[i * 132 + h] * g_kg[si * 128 + h];
        g_kqg[i * 4 + si] = a;
    }
    if (t < 4) {
        float a = 0.f;
        for (int h = 0; h < 128; ++h) a += bq_g[h] * g_kg[t * 128 + h];
        g_cgs[t] = a;
    }
}

// ---------------- kernel 3: fused per-edge kernel (256 thr, 2 CTA/SM) ----
__global__ void __launch_bounds__(256, 2)
main_edge_kernel(const float* __restrict__ ea_g,
                 const float* __restrict__ gf,
                 const int* __restrict__ ei,
                 const float* __restrict__ bo_g,
                 float* __restrict__ out,
                 float* __restrict__ attn_out) {
    extern __shared__ float smem[];
    unsigned* sEAhi = (unsigned*)smem;            // 64*68 uints
    unsigned* sEAlo = sEAhi + 64 * EA_U;          // 64*68 uints
    float*    sQK   = smem + 2 * 64 * EA_U;       // 64*260 floats
    const int tid  = threadIdx.x;
    const int wid  = tid >> 5;    // 0..7
    const int lane = tid & 31;
    const int g    = lane >> 2;   // 0..7
    const int t4   = lane & 3;    // 0..3
    const int e0   = blockIdx.x * TILE_E;

    // stage edge_attr tile pre-split to bf16 hi/lo (zero-fill OOB rows)
    for (int idx = tid; idx < 2048; idx += 256) {
        int r = idx >> 5, c = idx & 31;          // c: float4 col (k = 4c)
        float4 v = make_float4(0.f, 0.f, 0.f, 0.f);
        if (e0 + r < E_TOT) v = ((const float4*)ea_g)[(size_t)(e0 + r) * 32 + c];
        unsigned h0, l0, h1, l1;
        split_bf2(v.x, v.y, h0, l0);
        split_bf2(v.z, v.w, h1, l1);
        sEAhi[r * EA_U + 2 * c]     = h0;
        sEAhi[r * EA_U + 2 * c + 1] = h1;
        sEAlo[r * EA_U + 2 * c]     = l0;
        sEAlo[r * EA_U + 2 * c + 1] = l1;
    }
    __syncthreads();

    // ---- Phase A: qk[64][256] = ea @ C + c0 (bf16 m16n8k16, 3-term) ----
    // warps: 2m x 4n; warp tile m32 x n64; B from L2, pipelined 1 half-group ahead.
    {
        const int wm = wid >> 2;          // 0..1
        const int wn = wid & 3;           // 0..3
        const int m0 = wm * 32;
        const int n0 = wn * 64;
        float acc[2][8][4];
        #pragma unroll
        for (int am = 0; am < 2; ++am)
            #pragma unroll
            for (int bn = 0; bn < 8; ++bn)
                #pragma unroll
                for (int q = 0; q < 4; ++q) acc[am][bn][q] = 0.f;

        uint4 bpc[4], bpn[4];
        // preload (kg=0, hh=0)
        #pragma unroll
        for (int b2 = 0; b2 < 4; ++b2)
            bpc[b2] = __ldg(&g_Cb4[((n0 + 8 * b2 + g) * 8 + 0) * 4 + t4]);

        #pragma unroll 1
        for (int kg = 0; kg < 8; ++kg) {
            unsigned Ah[2][4], Al[2][4];
            #pragma unroll
            for (int am = 0; am < 2; ++am) {
                int R = m0 + 16 * am;
                Ah[am][0] = sEAhi[(R + g)     * EA_U + kg * 8 + t4];
                Ah[am][1] = sEAhi[(R + g + 8) * EA_U + kg * 8 + t4];
                Ah[am][2] = sEAhi[(R + g)     * EA_U + kg * 8 + 4 + t4];
                Ah[am][3] = sEAhi[(R + g + 8) * EA_U + kg * 8 + 4 + t4];
                Al[am][0] = sEAlo[(R + g)     * EA_U + kg * 8 + t4];
                Al[am][1] = sEAlo[(R + g + 8) * EA_U + kg * 8 + t4];
                Al[am][2] = sEAlo[(R + g)     * EA_U + kg * 8 + 4 + t4];
                Al[am][3] = sEAlo[(R + g + 8) * EA_U + kg * 8 + 4 + t4];
            }
            // prefetch hh=1 of this kg
            #pragma unroll
            for (int b2 = 0; b2 < 4; ++b2)
                bpn[b2] = __ldg(&g_Cb4[((n0 + 32 + 8 * b2 + g) * 8 + kg) * 4 + t4]);
            // compute hh=0 with bpc
            #pragma unroll
            for (int b2 = 0; b2 < 4; ++b2) {
                #pragma unroll
                for (int am = 0; am < 2; ++am) {
                    mma16(acc[am][b2], Ah[am], bpc[b2].x, bpc[b2].y);
                    mma16(acc[am][b2], Ah[am], bpc[b2].z, bpc[b2].w);
                    mma16(acc[am][b2], Al[am], bpc[b2].x, bpc[b2].y);
                }
            }
            // prefetch (kg+1, hh=0)
            if (kg < 7) {
                #pragma unroll
                for (int b2 = 0; b2 < 4; ++b2)
                    bpc[b2] = __ldg(&g_Cb4[((n0 + 8 * b2 + g) * 8 + kg + 1) * 4 + t4]);
            }
            // compute hh=1 with bpn
            #pragma unroll
            for (int b2 = 0; b2 < 4; ++b2) {
                #pragma unroll
                for (int am = 0; am < 2; ++am) {
                    mma16(acc[am][4 + b2], Ah[am], bpn[b2].x, bpn[b2].y);
                    mma16(acc[am][4 + b2], Ah[am], bpn[b2].z, bpn[b2].w);
                    mma16(acc[am][4 + b2], Al[am], bpn[b2].x, bpn[b2].y);
                }
            }
        }

        // epilogue: qk + c0 -> sQK
        #pragma unroll
        for (int am = 0; am < 2; ++am) {
            #pragma unroll
            for (int bn = 0; bn < 8; ++bn) {
                int col = n0 + 8 * bn + 2 * t4;
                float2 c0v = *(const float2*)&g_c0[col];
                int r1 = m0 + 16 * am + g;
                *(float2*)&sQK[r1 * QK_S + col] =
                    make_float2(acc[am][bn][0] + c0v.x, acc[am][bn][1] + c0v.y);
                *(float2*)&sQK[(r1 + 8) * QK_S + col] =
                    make_float2(acc[am][bn][2] + c0v.x, acc[am][bn][3] + c0v.y);
            }
        }
    }
    __syncthreads();

    // ---- Phase B: gather + local softmax + pooled feats + global path ----
    #pragma unroll 1
    for (int r = 0; r < 8; ++r) {
        int el = 8 * wid + r;
        int eg = e0 + el;
        if (eg < E_TOT) {
            int i0 = ei[eg];
            int i1 = ei[E_TOT + eg];
            const float4* srcp = (const float4*)(gf + (size_t)i0 * 512);
            const float4* dstp = (const float4*)(gf + (size_t)i1 * 512);
            // issue all 8 gather loads first
            float4 sv[4], dv[4];
            #pragma unroll
            for (int s2 = 0; s2 < 4; ++s2) {
                sv[s2] = srcp[s2 * 32 + lane];
                dv[s2] = dstp[s2 * 32 + lane];
            }

            // gather-independent work under the loads:
            // reconstruct edge_attr from hi+lo
            unsigned hu0 = sEAhi[el * EA_U + 2 * lane];
            unsigned hu1 = sEAhi[el * EA_U + 2 * lane + 1];
            unsigned lu0 = sEAlo[el * EA_U + 2 * lane];
            unsigned lu1 = sEAlo[el * EA_U + 2 * lane + 1];
            float2 hf0 = __bfloat1622float2(u_as_bf2(hu0));
            float2 hf1 = __bfloat1622float2(u_as_bf2(hu1));
            float2 lf0 = __bfloat1622float2(u_as_bf2(lu0));
            float2 lf1 = __bfloat1622float2(u_as_bf2(lu1));
            float4 eav = make_float4(hf0.x + lf0.x, hf0.y + lf0.y,
                                     hf1.x + lf1.x, hf1.y + lf1.y);
            // global-path partials
            float4 kq0 = ((const float4*)g_kqg)[4 * lane + 0];
            float4 kq1 = ((const float4*)g_kqg)[4 * lane + 1];
            float4 kq2 = ((const float4*)g_kqg)[4 * lane + 2];
            float4 kq3 = ((const float4*)g_kqg)[4 * lane + 3];
            float g0 = eav.x*kq0.x + eav.y*kq1.x + eav.z*kq2.x + eav.w*kq3.x;
            float g1 = eav.x*kq0.y + eav.y*kq1.y + eav.z*kq2.y + eav.w*kq3.y;
            float g2 = eav.x*kq0.z + eav.y*kq1.z + eav.z*kq2.z + eav.w*kq3.z;
            float g3 = eav.x*kq0.w + eav.y*kq1.w + eav.z*kq2.w + eav.w*kq3.w;
            float4 qlo = *(const float4*)&sQK[el * QK_S + 4 * lane];
            float4 qhi = *(const float4*)&sQK[el * QK_S + 128 + 4 * lane];

            // local score partials (first use of gathered data)
            float sc0 = dot4(qlo, sv[0]) + dot4(qhi, dv[0]);
            float sc1 = dot4(qlo, sv[1]) + dot4(qhi, dv[1]);
            float sc2 = dot4(qlo, sv[2]) + dot4(qhi, dv[2]);
            float sc3 = dot4(qlo, sv[3]) + dot4(qhi, dv[3]);

            // merged 8-value butterfly reduction
            #pragma unroll
            for (int o = 16; o > 0; o >>= 1) {
                sc0 += __shfl_xor_sync(0xFFFFFFFFu, sc0, o);
                sc1 += __shfl_xor_sync(0xFFFFFFFFu, sc1, o);
                sc2 += __shfl_xor_sync(0xFFFFFFFFu, sc2, o);
                sc3 += __shfl_xor_sync(0xFFFFFFFFu, sc3, o);
                g0  += __shfl_xor_sync(0xFFFFFFFFu, g0, o);
                g1  += __shfl_xor_sync(0xFFFFFFFFu, g1, o);
                g2  += __shfl_xor_sync(0xFFFFFFFFu, g2, o);
                g3  += __shfl_xor_sync(0xFFFFFFFFu, g3, o);
            }

            // local softmax + pooled features
            float z0 = sc0 * SCALE, z1 = sc1 * SCALE, z2 = sc2 * SCALE, z3 = sc3 * SCALE;
            float mz = fmaxf(fmaxf(z0, z1), fmaxf(z2, z3));
            float a0 = __expf(z0 - mz), a1 = __expf(z1 - mz);
            float a2 = __expf(z2 - mz), a3 = __expf(z3 - mz);
            float inv = 1.f / (a0 + a1 + a2 + a3);
            a0 *= inv; a1 *= inv; a2 *= inv; a3 *= inv;
            float4 plo, phi;
            plo.x = a0*sv[0].x + a1*sv[1].x + a2*sv[2].x + a3*sv[3].x;
            plo.y = a0*sv[0].y + a1*sv[1].y + a2*sv[2].y + a3*sv[3].y;
            plo.z = a0*sv[0].z + a1*sv[1].z + a2*sv[2].z + a3*sv[3].z;
            plo.w = a0*sv[0].w + a1*sv[1].w + a2*sv[2].w + a3*sv[3].w;
            phi.x = a0*dv[0].x + a1*dv[1].x + a2*dv[2].x + a3*dv[3].x;
            phi.y = a0*dv[0].y + a1*dv[1].y + a2*dv[2].y + a3*dv[3].y;
            phi.z = a0*dv[0].z + a1*dv[1].z + a2*dv[2].z + a3*dv[3].z;
            phi.w = a0*dv[0].w + a1*dv[1].w + a2*dv[2].w + a3*dv[3].w;
            *(float4*)&sQK[el * QK_S + 4 * lane] = plo;         // in-place pooled
            *(float4*)&sQK[el * QK_S + 128 + 4 * lane] = phi;

            // global softmax + output
            float y0 = (g0 + g_cgs[0]) * SCALE, y1 = (g1 + g_cgs[1]) * SCALE;
            float y2 = (g2 + g_cgs[2]) * SCALE, y3 = (g3 + g_cgs[3]) * SCALE;
            float my = fmaxf(fmaxf(y0, y1), fmaxf(y2, y3));
            float b0 = __expf(y0 - my), b1 = __expf(y1 - my);
            float b2 = __expf(y2 - my), b3 = __expf(y3 - my);
            float binv = 1.f / (b0 + b1 + b2 + b3);
            b0 *= binv; b1 *= binv; b2 *= binv; b3 *= binv;
            if (lane == 0) {
                float* ap = attn_out + (size_t)eg * 4;
                ap[0] = b0; ap[1] = b1; ap[2] = b2; ap[3] = b3;
            }
            float4 m0v = ((const float4*)g_M)[lane];
            float4 m1v = ((const float4*)g_M)[32 + lane];
            float4 m2v = ((const float4*)g_M)[64 + lane];
            float4 m3v = ((const float4*)g_M)[96 + lane];
            float4 bo4 = ((const float4*)bo_g)[lane];
            float4 go;
            go.x = b0*m0v.x + b1*m1v.x + b2*m2v.x + b3*m3v.x + bo4.x;
            go.y = b0*m0v.y + b1*m1v.y + b2*m2v.y + b3*m3v.y + bo4.y;
            go.z = b0*m0v.z + b1*m1v.z + b2*m2v.z + b3*m3v.z + bo4.z;
            go.w = b0*m0v.w + b1*m1v.w + b2*m2v.w + b3*m3v.w + bo4.w;
            float* orow = out + (size_t)eg * 384;
            ((float4*)orow)[lane] = eav;
            ((float4*)(orow + 256))[lane] = go;
        }
    }
    __syncthreads();

    // ---- Phase C: local_out[64][128] = pooled @ W2^T + bias2 (bf16) ----
    // warps: 2m x 4n; warp tile m32 x n32; B pipelined 1 kg ahead.
    {
        const int cm = wid >> 2;         // 0..1
        const int cn = wid & 3;          // 0..3
        const int m0 = cm * 32;
        const int n0 = cn * 32;
        float acc[2][4][4];
        #pragma unroll
        for (int am = 0; am < 2; ++am)
            #pragma unroll
            for (int bn = 0; bn < 4; ++bn)
                #pragma unroll
                for (int q = 0; q < 4; ++q) acc[am][bn][q] = 0.f;

        uint4 bp0[4], bp1[4];
        #pragma unroll
        for (int bn = 0; bn < 4; ++bn)
            bp0[bn] = __ldg(&g_W2b4[((n0 + 8 * bn + g) * 16 + 0) * 4 + t4]);

        #pragma unroll 1
        for (int kg = 0; kg < 16; kg += 2) {
            // prefetch kg+1
            #pragma unroll
            for (int bn = 0; bn < 4; ++bn)
                bp1[bn] = __ldg(&g_W2b4[((n0 + 8 * bn + g) * 16 + kg + 1) * 4 + t4]);

            // compute kg with bp0
            {
                unsigned Ah[2][4], Al[2][4];
                #pragma unroll
                for (int am = 0; am < 2; ++am) {
                    int R = m0 + 16 * am;
                    float2 p00 = *(const float2*)&sQK[(R + g)     * QK_S + kg * 16 + 2 * t4];
                    float2 p10 = *(const float2*)&sQK[(R + g + 8) * QK_S + kg * 16 + 2 * t4];
                    float2 p01 = *(const float2*)&sQK[(R + g)     * QK_S + kg * 16 + 2 * t4 + 8];
                    float2 p11 = *(const float2*)&sQK[(R + g + 8) * QK_S + kg * 16 + 2 * t4 + 8];
                    split_bf2(p00.x, p00.y, Ah[am][0], Al[am][0]);
                    split_bf2(p10.x, p10.y, Ah[am][1], Al[am][1]);
                    split_bf2(p01.x, p01.y, Ah[am][2], Al[am][2]);
                    split_bf2(p11.x, p11.y, Ah[am][3], Al[am][3]);
                }
                #pragma unroll
                for (int bn = 0; bn < 4; ++bn) {
                    #pragma unroll
                    for (int am = 0; am < 2; ++am) {
                        mma16(acc[am][bn], Ah[am], bp0[bn].x, bp0[bn].y);
                        mma16(acc[am][bn], Ah[am], bp0[bn].z, bp0[bn].w);
                        mma16(acc[am][bn], Al[am], bp0[bn].x, bp0[bn].y);
                    }
                }
            }

            // prefetch kg+2
            if (kg + 2 < 16) {
                #pragma unroll
                for (int bn = 0; bn < 4; ++bn)
                    bp0[bn] = __ldg(&g_W2b4[((n0 + 8 * bn + g) * 16 + kg + 2) * 4 + t4]);
            }

            // compute kg+1 with bp1
            {
                unsigned Ah[2][4], Al[2][4];
                #pragma unroll
                for (int am = 0; am < 2; ++am) {
                    int R = m0 + 16 * am;
                    float2 p00 = *(const float2*)&sQK[(R + g)     * QK_S + (kg+1) * 16 + 2 * t4];
                    float2 p10 = *(const float2*)&sQK[(R + g + 8) * QK_S + (kg+1) * 16 + 2 * t4];
                    float2 p01 = *(const float2*)&sQK[(R + g)     * QK_S + (kg+1) * 16 + 2 * t4 + 8];
                    float2 p11 = *(const float2*)&sQK[(R + g + 8) * QK_S + (kg+1) * 16 + 2 * t4 + 8];
                    split_bf2(p00.x, p00.y, Ah[am][0], Al[am][0]);
                    split_bf2(p10.x, p10.y, Ah[am][1], Al[am][1]);
                    split_bf2(p01.x, p01.y, Ah[am][2], Al[am][2]);
                    split_bf2(p11.x, p11.y, Ah[am][3], Al[am][3]);
                }
                #pragma unroll
                for (int bn = 0; bn < 4; ++bn) {
                    #pragma unroll
                    for (int am = 0; am < 2; ++am) {
                        mma16(acc[am][bn], Ah[am], bp1[bn].x, bp1[bn].y);
                        mma16(acc[am][bn], Ah[am], bp1[bn].z, bp1[bn].w);
                        mma16(acc[am][bn], Al[am], bp1[bn].x, bp1[bn].y);
                    }
                }
            }
        }

        // epilogue: + bias2 -> out[:, 128:256]
        #pragma unroll
        for (int am = 0; am < 2; ++am) {
            #pragma unroll
            for (int bn = 0; bn < 4; ++bn) {
                int h = n0 + 8 * bn + 2 * t4;
                float2 bv = *(const float2*)&g_bias2[h];
                int e1 = e0 + m0 + 16 * am + g;
                if (e1 < E_TOT) {
                    *(float2*)&out[(size_t)e1 * 384 + 128 + h] =
                        make_float2(acc[am][bn][0] + bv.x, acc[am][bn][1] + bv.y);
                }
                int e2 = e1 + 8;
                if (e2 < E_TOT) {
                    *(float2*)&out[(size_t)e2 * 384 + 128 + h] =
                        make_float2(acc[am][bn][2] + bv.x, acc[am][bn][3] + bv.y);
                }
            }
        }
    }
}

// ---------------- launch ---------------------------------------------------
extern "C" void kernel_launch(void* const* d_in, const int* in_sizes, int n_in,
                              void* d_out, int out_size) {
    const float* ea   = (const float*)d_in[0];
    const float* gf   = (const float*)d_in[1];
    const int*   ei   = (const int*)d_in[2];
    const float* wq_l = (const float*)d_in[3];
    const float* wk_l = (const float*)d_in[4];
    const float* wv_l = (const float*)d_in[5];
    const float* bq_l = (const float*)d_in[6];
    const float* bv_l = (const float*)d_in[8];
    const float* wo_l = (const float*)d_in[9];
    const float* bo_l = (const float*)d_in[10];
    const float* wq_g = (const float*)d_in[11];
    const float* wk_g = (const float*)d_in[12];
    const float* wv_g = (const float*)d_in[13];
    const float* bq_g = (const float*)d_in[14];
    const float* bk_g = (const float*)d_in[15];
    const float* bv_g = (const float*)d_in[16];
    const float* wo_g = (const float*)d_in[17];
    const float* bo_g = (const float*)d_in[18];

    float* out        = (float*)d_out;
    float* out_pooled = out + (size_t)E_TOT * 384;
    float* out_attn   = out_pooled + 512;

    const int MAIN_SMEM = (2 * 64 * EA_U + 16640) * 4;   // 101376 B

    cudaFuncSetAttribute(k1_precompute,
                         cudaFuncAttributeMaxDynamicSharedMemorySize, 67584);
    cudaFuncSetAttribute(k2_small,
                         cudaFuncAttributeMaxDynamicSharedMemorySize, 67584);
    cudaFuncSetAttribute(main_edge_kernel,
                         cudaFuncAttributeMaxDynamicSharedMemorySize, MAIN_SMEM);

    k1_precompute<<<POOL_BLKS + 386, 512, 67584>>>(gf, wq_l, wk_l, wv_l, wo_l,
                                                   bq_l, bv_l, bo_l);
    k2_small<<<1, 512, 67584>>>(wk_g, wv_g, wo_g, wq_g,
                                bk_g, bv_g, bq_g, out_pooled);
    main_edge_kernel<<<GRID_MAIN, 256, MAIN_SMEM>>>(ea, gf, ei, bo_g, out, out_attn);
}

// round 9
// speedup vs baseline: 2.9620x; 1.0390x over previous
#include <cuda_runtime.h>
#include <cuda_bf16.h>

#define E_TOT   100000
#define NN      50000
#define POOL_BLKS 592
#define ROWS_PER_BLK 85
#define TILE_E  64
#define GRID_MAIN ((E_TOT + TILE_E - 1) / TILE_E)
#define EA_U    68      /* sEAhi/sEAlo row stride in uints (64 data + 4 pad) */
#define QK_S    260     /* sQK row stride (floats) */
#define SCALE   0.08838834764831845f   /* 1/sqrt(128) */

// ---------------- device scratch ----------------
__device__ float g_partial[POOL_BLKS * 512];
__device__ float g_pooled[512];
__device__ float g_kg[512];
__device__ float g_vg[512];
__device__ float g_M[512];          // [4][128] = v_g @ wo_g^T
__device__ float g_kqg[512];        // [128][4]
__device__ float g_cgs[4];
__device__ float g_c0[256];         // bq_l @ wk_l
__device__ float g_bias2[128];      // bv_l @ wo_l^T + bo_l
__device__ unsigned int g_poolctr;  // monotonic last-block counter (replay-safe via modulo)
// B matrices pre-split to bf16 hi/lo in m16n8k16 fragment order:
// uint4 per (n, kg, t4) = {hi_k(2t4,2t4+1), hi_k(+8,+9), lo_k01, lo_k89}
__device__ uint4 g_Cb4[256 * 8 * 4];    // C:  n=256, k=128 (kg 0..7)
__device__ uint4 g_W2b4[128 * 16 * 4];  // W2: n=128, k=256 (kg 0..15)

__device__ __forceinline__ float dot4(float4 a, float4 b) {
    return a.x * b.x + a.y * b.y + a.z * b.z + a.w * b.w;
}

__device__ __forceinline__ void mma16(float* d, const unsigned* a, unsigned b0, unsigned b1) {
    asm volatile(
        "mma.sync.aligned.m16n8k16.row.col.f32.bf16.bf16.f32 "
        "{%0,%1,%2,%3}, {%4,%5,%6,%7}, {%8,%9}, {%0,%1,%2,%3};"
        : "+f"(d[0]), "+f"(d[1]), "+f"(d[2]), "+f"(d[3])
        : "r"(a[0]), "r"(a[1]), "r"(a[2]), "r"(a[3]), "r"(b0), "r"(b1));
}

__device__ __forceinline__ unsigned bf2_as_u(__nv_bfloat162 h) {
    return *(unsigned*)&h;
}
__device__ __forceinline__ __nv_bfloat162 u_as_bf2(unsigned u) {
    return *(__nv_bfloat162*)&u;
}

// split float pair -> hi bf16x2, lo bf16x2
__device__ __forceinline__ void split_bf2(float x, float y, unsigned& hi, unsigned& lo) {
    __nv_bfloat162 h = __float22bfloat162_rn(make_float2(x, y));
    float2 hf = __bfloat1622float2(h);
    __nv_bfloat162 l = __float22bfloat162_rn(make_float2(x - hf.x, y - hf.y));
    hi = bf2_as_u(h);
    lo = bf2_as_u(l);
}

// write one fp32 value as pre-split bf16 hi/lo into fragment-ordered array.
__device__ __forceinline__ void write_b_split(__nv_bfloat16* base, int n, int k,
                                              int kgs, float v) {
    int kg = k >> 4, r = k & 15;
    int word, t4;
    if (r < 8) { t4 = r >> 1; word = 0; }
    else       { t4 = (r - 8) >> 1; word = 1; }
    int half = r & 1;
    size_t bidx = ((((size_t)(n * kgs + kg) * 4 + t4) * 4 + word) * 2 + half);
    __nv_bfloat16 hi = __float2bfloat16(v);
    __nv_bfloat16 lo = __float2bfloat16(v - __bfloat162float(hi));
    base[bidx] = hi;
    base[bidx + 4] = lo;
}

// ---------------- kernel 1: everything precomputed -----------------------
// blocks 0..591: pool partial (last-finishing one also runs the k2 body);
// 592..719: C k-rows; 720..975: W2 k-rows; 976: c0; 977: bias2.
__global__ void k1_precompute(const float* __restrict__ gf,
                              const float* __restrict__ wq_l,
                              const float* __restrict__ wk_l,
                              const float* __restrict__ wv_l,
                              const float* __restrict__ wo_l,
                              const float* __restrict__ bq_l,
                              const float* __restrict__ bv_l,
                              const float* __restrict__ bo_l,
                              const float* __restrict__ wk_g,
                              const float* __restrict__ wv_g,
                              const float* __restrict__ wo_g,
                              const float* __restrict__ wq_g,
                              const float* __restrict__ bk_g,
                              const float* __restrict__ bv_g,
                              const float* __restrict__ bq_g,
                              float* __restrict__ out_pooled) {
    extern __shared__ float st[];
    __shared__ int s_islast;
    int b = blockIdx.x, t = threadIdx.x;
    if (b < POOL_BLKS) {
        int r0 = b * ROWS_PER_BLK;
        int nrows = NN - r0;
        if (nrows > ROWS_PER_BLK) nrows = ROWS_PER_BLK;
        const float* p = gf + (size_t)r0 * 512 + t;
        float s0 = 0.f, s1 = 0.f, s2 = 0.f, s3 = 0.f;
        int r = 0;
        for (; r + 4 <= nrows; r += 4) {
            s0 += p[(size_t)r * 512];
            s1 += p[(size_t)(r + 1) * 512];
            s2 += p[(size_t)(r + 2) * 512];
            s3 += p[(size_t)(r + 3) * 512];
        }
        for (; r < nrows; ++r) s0 += p[(size_t)r * 512];
        g_partial[b * 512 + t] = (s0 + s1) + (s2 + s3);
        __threadfence();
        __syncthreads();
        if (t == 0) {
            unsigned old = atomicAdd(&g_poolctr, 1u);
            s_islast = ((old % POOL_BLKS) == POOL_BLKS - 1) ? 1 : 0;
        }
        __syncthreads();
        if (s_islast) {
            // ---- k2 body: pooled + global-path small matrices ----
            __threadfence();
            float s = 0.f;
            for (int bb = 0; bb < POOL_BLKS; ++bb) s += g_partial[bb * 512 + t];
            s *= (1.0f / NN);
            g_pooled[t] = s;
            out_pooled[t] = s;
            __syncthreads();

            for (int idx = t; idx < 16384; idx += 512) {
                int h = idx >> 7, j = idx & 127; st[j * 132 + h] = wk_g[idx];
            }
            __syncthreads();
            {
                int si = t >> 7, h = t & 127; float a = 0.f;
                for (int j = 0; j < 128; ++j) a += g_pooled[si * 128 + j] * st[j * 132 + h];
                g_kg[t] = a + bk_g[h];
            }
            __syncthreads();

            for (int idx = t; idx < 16384; idx += 512) {
                int h = idx >> 7, j = idx & 127; st[j * 132 + h] = wv_g[idx];
            }
            __syncthreads();
            {
                int si = t >> 7, h = t & 127; float a = 0.f;
                for (int j = 0; j < 128; ++j) a += g_pooled[si * 128 + j] * st[j * 132 + h];
                g_vg[t] = a + bv_g[h];
            }
            __syncthreads();

            for (int idx = t; idx < 16384; idx += 512) {
                int h = idx >> 7, m = idx & 127; st[m * 132 + h] = wo_g[idx];
            }
            __syncthreads();
            {
                int si = t >> 7, h = t & 127; float a = 0.f;
                for (int m = 0; m < 128; ++m) a += g_vg[si * 128 + m] * st[m * 132 + h];
                g_M[t] = a;
            }
            __syncthreads();

            for (int idx = t; idx < 16384; idx += 512) {
                int h = idx >> 7, i = idx & 127; st[i * 132 + h] = wq_g[idx];
            }
            __syncthreads();
            {
                int i = t >> 2, si = t & 3; float a = 0.f;
                for (int h = 0; h < 128; ++h) a += st[i * 132 + h] * g_kg[si * 128 + h];
                g_kqg[i * 4 + si] = a;
            }
            if (t < 4) {
                float a = 0.f;
                for (int h = 0; h < 128; ++h) a += bq_g[h] * g_kg[t * 128 + h];
                g_cgs[t] = a;
            }
        }
    } else if (b < POOL_BLKS + 128) {
        int i = b - POOL_BLKS;      // C k-row 0..127
        if (t < 256) {
            float a = 0.f;
            for (int h = 0; h < 128; ++h)
                a += __ldg(&wq_l[h * 128 + i]) * wk_l[h * 256 + t];
            write_b_split((__nv_bfloat16*)g_Cb4, t, i, 8, a);
        }
    } else if (b < POOL_BLKS + 384) {
        int j = b - (POOL_BLKS + 128);   // W2 k-index 0..255
        for (int idx = t; idx < 16384; idx += 512) {
            int h = idx >> 7, m = idx & 127;
            st[m * 132 + h] = wo_l[idx];
        }
        __syncthreads();
        if (t < 128) {
            float a = 0.f;
            for (int m = 0; m < 128; ++m)
                a += __ldg(&wv_l[m * 256 + j]) * st[m * 132 + t];
            write_b_split((__nv_bfloat16*)g_W2b4, t, j, 16, a);
        }
    } else if (b == POOL_BLKS + 384) {
        if (t < 256) {
            float a = 0.f;
            for (int h = 0; h < 128; ++h) a += bq_l[h] * wk_l[h * 256 + t];
            g_c0[t] = a;
        }
    } else {
        for (int idx = t; idx < 16384; idx += 512) {
            int h = idx >> 7, m = idx & 127;
            st[m * 132 + h] = wo_l[idx];
        }
        __syncthreads();
        if (t < 128) {
            float a = 0.f;
            for (int m = 0; m < 128; ++m) a += bv_l[m] * st[m * 132 + t];
            g_bias2[t] = a + bo_l[t];
        }
    }
}

// ---------------- kernel 2: fused per-edge kernel (256 thr, 2 CTA/SM) ----
__global__ void __launch_bounds__(256, 2)
main_edge_kernel(const float* __restrict__ ea_g,
                 const float* __restrict__ gf,
                 const int* __restrict__ ei,
                 const float* __restrict__ bo_g,
                 float* __restrict__ out,
                 float* __restrict__ attn_out) {
    extern __shared__ float smem[];
    unsigned* sEAhi = (unsigned*)smem;            // 64*68 uints
    unsigned* sEAlo = sEAhi + 64 * EA_U;          // 64*68 uints
    float*    sQK   = smem + 2 * 64 * EA_U;       // 64*260 floats
    const int tid  = threadIdx.x;
    const int wid  = tid >> 5;    // 0..7
    const int lane = tid & 31;
    const int g    = lane >> 2;   // 0..7
    const int t4   = lane & 3;    // 0..3
    const int e0   = blockIdx.x * TILE_E;

    // stage edge_attr tile pre-split to bf16 hi/lo (zero-fill OOB rows)
    for (int idx = tid; idx < 2048; idx += 256) {
        int r = idx >> 5, c = idx & 31;          // c: float4 col (k = 4c)
        float4 v = make_float4(0.f, 0.f, 0.f, 0.f);
        if (e0 + r < E_TOT) v = ((const float4*)ea_g)[(size_t)(e0 + r) * 32 + c];
        unsigned h0, l0, h1, l1;
        split_bf2(v.x, v.y, h0, l0);
        split_bf2(v.z, v.w, h1, l1);
        sEAhi[r * EA_U + 2 * c]     = h0;
        sEAhi[r * EA_U + 2 * c + 1] = h1;
        sEAlo[r * EA_U + 2 * c]     = l0;
        sEAlo[r * EA_U + 2 * c + 1] = l1;
    }
    __syncthreads();

    // ---- Phase A: qk[64][256] = ea @ C + c0 (bf16 m16n8k16, 3-term) ----
    {
        const int wm = wid >> 2;          // 0..1
        const int wn = wid & 3;           // 0..3
        const int m0 = wm * 32;
        const int n0 = wn * 64;
        float acc[2][8][4];
        #pragma unroll
        for (int am = 0; am < 2; ++am)
            #pragma unroll
            for (int bn = 0; bn < 8; ++bn)
                #pragma unroll
                for (int q = 0; q < 4; ++q) acc[am][bn][q] = 0.f;

        uint4 bpc[4], bpn[4];
        #pragma unroll
        for (int b2 = 0; b2 < 4; ++b2)
            bpc[b2] = __ldg(&g_Cb4[((n0 + 8 * b2 + g) * 8 + 0) * 4 + t4]);

        #pragma unroll 1
        for (int kg = 0; kg < 8; ++kg) {
            unsigned Ah[2][4], Al[2][4];
            #pragma unroll
            for (int am = 0; am < 2; ++am) {
                int R = m0 + 16 * am;
                Ah[am][0] = sEAhi[(R + g)     * EA_U + kg * 8 + t4];
                Ah[am][1] = sEAhi[(R + g + 8) * EA_U + kg * 8 + t4];
                Ah[am][2] = sEAhi[(R + g)     * EA_U + kg * 8 + 4 + t4];
                Ah[am][3] = sEAhi[(R + g + 8) * EA_U + kg * 8 + 4 + t4];
                Al[am][0] = sEAlo[(R + g)     * EA_U + kg * 8 + t4];
                Al[am][1] = sEAlo[(R + g + 8) * EA_U + kg * 8 + t4];
                Al[am][2] = sEAlo[(R + g)     * EA_U + kg * 8 + 4 + t4];
                Al[am][3] = sEAlo[(R + g + 8) * EA_U + kg * 8 + 4 + t4];
            }
            #pragma unroll
            for (int b2 = 0; b2 < 4; ++b2)
                bpn[b2] = __ldg(&g_Cb4[((n0 + 32 + 8 * b2 + g) * 8 + kg) * 4 + t4]);
            #pragma unroll
            for (int b2 = 0; b2 < 4; ++b2) {
                #pragma unroll
                for (int am = 0; am < 2; ++am) {
                    mma16(acc[am][b2], Ah[am], bpc[b2].x, bpc[b2].y);
                    mma16(acc[am][b2], Ah[am], bpc[b2].z, bpc[b2].w);
                    mma16(acc[am][b2], Al[am], bpc[b2].x, bpc[b2].y);
                }
            }
            if (kg < 7) {
                #pragma unroll
                for (int b2 = 0; b2 < 4; ++b2)
                    bpc[b2] = __ldg(&g_Cb4[((n0 + 8 * b2 + g) * 8 + kg + 1) * 4 + t4]);
            }
            #pragma unroll
            for (int b2 = 0; b2 < 4; ++b2) {
                #pragma unroll
                for (int am = 0; am < 2; ++am) {
                    mma16(acc[am][4 + b2], Ah[am], bpn[b2].x, bpn[b2].y);
                    mma16(acc[am][4 + b2], Ah[am], bpn[b2].z, bpn[b2].w);
                    mma16(acc[am][4 + b2], Al[am], bpn[b2].x, bpn[b2].y);
                }
            }
        }

        // epilogue: qk + c0 -> sQK
        #pragma unroll
        for (int am = 0; am < 2; ++am) {
            #pragma unroll
            for (int bn = 0; bn < 8; ++bn) {
                int col = n0 + 8 * bn + 2 * t4;
                float2 c0v = *(const float2*)&g_c0[col];
                int r1 = m0 + 16 * am + g;
                *(float2*)&sQK[r1 * QK_S + col] =
                    make_float2(acc[am][bn][0] + c0v.x, acc[am][bn][1] + c0v.y);
                *(float2*)&sQK[(r1 + 8) * QK_S + col] =
                    make_float2(acc[am][bn][2] + c0v.x, acc[am][bn][3] + c0v.y);
            }
        }
    }
    __syncthreads();

    // ---- Phase B: gather + local softmax + pooled feats + global path ----
    int idx0[8], idx1[8];
    #pragma unroll
    for (int r = 0; r < 8; ++r) {
        int eg = e0 + 8 * wid + r;
        int egc = eg < E_TOT ? eg : E_TOT - 1;
        idx0[r] = ei[egc];
        idx1[r] = ei[E_TOT + egc];
    }
    #pragma unroll 2
    for (int r = 0; r < 8; ++r) {
        int el = 8 * wid + r;
        int eg = e0 + el;
        if (eg < E_TOT) {
            const float4* srcp = (const float4*)(gf + (size_t)idx0[r] * 512);
            const float4* dstp = (const float4*)(gf + (size_t)idx1[r] * 512);
            float4 sv[4], dv[4];
            #pragma unroll
            for (int s2 = 0; s2 < 4; ++s2) {
                sv[s2] = srcp[s2 * 32 + lane];
                dv[s2] = dstp[s2 * 32 + lane];
            }

            // gather-independent work under the loads
            unsigned hu0 = sEAhi[el * EA_U + 2 * lane];
            unsigned hu1 = sEAhi[el * EA_U + 2 * lane + 1];
            unsigned lu0 = sEAlo[el * EA_U + 2 * lane];
            unsigned lu1 = sEAlo[el * EA_U + 2 * lane + 1];
            float2 hf0 = __bfloat1622float2(u_as_bf2(hu0));
            float2 hf1 = __bfloat1622float2(u_as_bf2(hu1));
            float2 lf0 = __bfloat1622float2(u_as_bf2(lu0));
            float2 lf1 = __bfloat1622float2(u_as_bf2(lu1));
            float4 eav = make_float4(hf0.x + lf0.x, hf0.y + lf0.y,
                                     hf1.x + lf1.x, hf1.y + lf1.y);
            float4 kq0 = ((const float4*)g_kqg)[4 * lane + 0];
            float4 kq1 = ((const float4*)g_kqg)[4 * lane + 1];
            float4 kq2 = ((const float4*)g_kqg)[4 * lane + 2];
            float4 kq3 = ((const float4*)g_kqg)[4 * lane + 3];
            float g0 = eav.x*kq0.x + eav.y*kq1.x + eav.z*kq2.x + eav.w*kq3.x;
            float g1 = eav.x*kq0.y + eav.y*kq1.y + eav.z*kq2.y + eav.w*kq3.y;
            float g2 = eav.x*kq0.z + eav.y*kq1.z + eav.z*kq2.z + eav.w*kq3.z;
            float g3 = eav.x*kq0.w + eav.y*kq1.w + eav.z*kq2.w + eav.w*kq3.w;
            float4 qlo = *(const float4*)&sQK[el * QK_S + 4 * lane];
            float4 qhi = *(const float4*)&sQK[el * QK_S + 128 + 4 * lane];

            float sc0 = dot4(qlo, sv[0]) + dot4(qhi, dv[0]);
            float sc1 = dot4(qlo, sv[1]) + dot4(qhi, dv[1]);
            float sc2 = dot4(qlo, sv[2]) + dot4(qhi, dv[2]);
            float sc3 = dot4(qlo, sv[3]) + dot4(qhi, dv[3]);

            // merged 8-value butterfly reduction
            #pragma unroll
            for (int o = 16; o > 0; o >>= 1) {
                sc0 += __shfl_xor_sync(0xFFFFFFFFu, sc0, o);
                sc1 += __shfl_xor_sync(0xFFFFFFFFu, sc1, o);
                sc2 += __shfl_xor_sync(0xFFFFFFFFu, sc2, o);
                sc3 += __shfl_xor_sync(0xFFFFFFFFu, sc3, o);
                g0  += __shfl_xor_sync(0xFFFFFFFFu, g0, o);
                g1  += __shfl_xor_sync(0xFFFFFFFFu, g1, o);
                g2  += __shfl_xor_sync(0xFFFFFFFFu, g2, o);
                g3  += __shfl_xor_sync(0xFFFFFFFFu, g3, o);
            }

            float z0 = sc0 * SCALE, z1 = sc1 * SCALE, z2 = sc2 * SCALE, z3 = sc3 * SCALE;
            float mz = fmaxf(fmaxf(z0, z1), fmaxf(z2, z3));
            float a0 = __expf(z0 - mz), a1 = __expf(z1 - mz);
            float a2 = __expf(z2 - mz), a3 = __expf(z3 - mz);
            float inv = 1.f / (a0 + a1 + a2 + a3);
            a0 *= inv; a1 *= inv; a2 *= inv; a3 *= inv;
            float4 plo, phi;
            plo.x = a0*sv[0].x + a1*sv[1].x + a2*sv[2].x + a3*sv[3].x;
            plo.y = a0*sv[0].y + a1*sv[1].y + a2*sv[2].y + a3*sv[3].y;
            plo.z = a0*sv[0].z + a1*sv[1].z + a2*sv[2].z + a3*sv[3].z;
            plo.w = a0*sv[0].w + a1*sv[1].w + a2*sv[2].w + a3*sv[3].w;
            phi.x = a0*dv[0].x + a1*dv[1].x + a2*dv[2].x + a3*dv[3].x;
            phi.y = a0*dv[0].y + a1*dv[1].y + a2*dv[2].y + a3*dv[3].y;
            phi.z = a0*dv[0].z + a1*dv[1].z + a2*dv[2].z + a3*dv[3].z;
            phi.w = a0*dv[0].w + a1*dv[1].w + a2*dv[2].w + a3*dv[3].w;
            *(float4*)&sQK[el * QK_S + 4 * lane] = plo;         // in-place pooled
            *(float4*)&sQK[el * QK_S + 128 + 4 * lane] = phi;

            float y0 = (g0 + g_cgs[0]) * SCALE, y1 = (g1 + g_cgs[1]) * SCALE;
            float y2 = (g2 + g_cgs[2]) * SCALE, y3 = (g3 + g_cgs[3]) * SCALE;
            float my = fmaxf(fmaxf(y0, y1), fmaxf(y2, y3));
            float b0 = __expf(y0 - my), b1 = __expf(y1 - my);
            float b2 = __expf(y2 - my), b3 = __expf(y3 - my);
            float binv = 1.f / (b0 + b1 + b2 + b3);
            b0 *= binv; b1 *= binv; b2 *= binv; b3 *= binv;
            if (lane == 0) {
                float* ap = attn_out + (size_t)eg * 4;
                ap[0] = b0; ap[1] = b1; ap[2] = b2; ap[3] = b3;
            }
            float4 m0v = ((const float4*)g_M)[lane];
            float4 m1v = ((const float4*)g_M)[32 + lane];
            float4 m2v = ((const float4*)g_M)[64 + lane];
            float4 m3v = ((const float4*)g_M)[96 + lane];
            float4 bo4 = ((const float4*)bo_g)[lane];
            float4 go;
            go.x = b0*m0v.x + b1*m1v.x + b2*m2v.x + b3*m3v.x + bo4.x;
            go.y = b0*m0v.y + b1*m1v.y + b2*m2v.y + b3*m3v.y + bo4.y;
            go.z = b0*m0v.z + b1*m1v.z + b2*m2v.z + b3*m3v.z + bo4.z;
            go.w = b0*m0v.w + b1*m1v.w + b2*m2v.w + b3*m3v.w + bo4.w;
            float* orow = out + (size_t)eg * 384;
            ((float4*)orow)[lane] = eav;
            ((float4*)(orow + 256))[lane] = go;
        }
    }
    __syncthreads();

    // ---- Phase C: local_out[64][128] = pooled @ W2^T + bias2 (bf16) ----
    {
        const int cm = wid >> 2;         // 0..1
        const int cn = wid & 3;          // 0..3
        const int m0 = cm * 32;
        const int n0 = cn * 32;
        float acc[2][4][4];
        #pragma unroll
        for (int am = 0; am < 2; ++am)
            #pragma unroll
            for (int bn = 0; bn < 4; ++bn)
                #pragma unroll
                for (int q = 0; q < 4; ++q) acc[am][bn][q] = 0.f;

        uint4 bp0[4], bp1[4];
        #pragma unroll
        for (int bn = 0; bn < 4; ++bn)
            bp0[bn] = __ldg(&g_W2b4[((n0 + 8 * bn + g) * 16 + 0) * 4 + t4]);

        #pragma unroll 1
        for (int kg = 0; kg < 16; kg += 2) {
            #pragma unroll
            for (int bn = 0; bn < 4; ++bn)
                bp1[bn] = __ldg(&g_W2b4[((n0 + 8 * bn + g) * 16 + kg + 1) * 4 + t4]);

            {
                unsigned Ah[2][4], Al[2][4];
                #pragma unroll
                for (int am = 0; am < 2; ++am) {
                    int R = m0 + 16 * am;
                    float2 p00 = *(const float2*)&sQK[(R + g)     * QK_S + kg * 16 + 2 * t4];
                    float2 p10 = *(const float2*)&sQK[(R + g + 8) * QK_S + kg * 16 + 2 * t4];
                    float2 p01 = *(const float2*)&sQK[(R + g)     * QK_S + kg * 16 + 2 * t4 + 8];
                    float2 p11 = *(const float2*)&sQK[(R + g + 8) * QK_S + kg * 16 + 2 * t4 + 8];
                    split_bf2(p00.x, p00.y, Ah[am][0], Al[am][0]);
                    split_bf2(p10.x, p10.y, Ah[am][1], Al[am][1]);
                    split_bf2(p01.x, p01.y, Ah[am][2], Al[am][2]);
                    split_bf2(p11.x, p11.y, Ah[am][3], Al[am][3]);
                }
                #pragma unroll
                for (int bn = 0; bn < 4; ++bn) {
                    #pragma unroll
                    for (int am = 0; am < 2; ++am) {
                        mma16(acc[am][bn], Ah[am], bp0[bn].x, bp0[bn].y);
                        mma16(acc[am][bn], Ah[am], bp0[bn].z, bp0[bn].w);
                        mma16(acc[am][bn], Al[am], bp0[bn].x, bp0[bn].y);
                    }
                }
            }

            if (kg + 2 < 16) {
                #pragma unroll
                for (int bn = 0; bn < 4; ++bn)
                    bp0[bn] = __ldg(&g_W2b4[((n0 + 8 * bn + g) * 16 + kg + 2) * 4 + t4]);
            }

            {
                unsigned Ah[2][4], Al[2][4];
                #pragma unroll
                for (int am = 0; am < 2; ++am) {
                    int R = m0 + 16 * am;
                    float2 p00 = *(const float2*)&sQK[(R + g)     * QK_S + (kg+1) * 16 + 2 * t4];
                    float2 p10 = *(const float2*)&sQK[(R + g + 8) * QK_S + (kg+1) * 16 + 2 * t4];
                    float2 p01 = *(const float2*)&sQK[(R + g)     * QK_S + (kg+1) * 16 + 2 * t4 + 8];
                    float2 p11 = *(const float2*)&sQK[(R + g + 8) * QK_S + (kg+1) * 16 + 2 * t4 + 8];
                    split_bf2(p00.x, p00.y, Ah[am][0], Al[am][0]);
                    split_bf2(p10.x, p10.y, Ah[am][1], Al[am][1]);
                    split_bf2(p01.x, p01.y, Ah[am][2], Al[am][2]);
                    split_bf2(p11.x, p11.y, Ah[am][3], Al[am][3]);
                }
                #pragma unroll
                for (int bn = 0; bn < 4; ++bn) {
                    #pragma unroll
                    for (int am = 0; am < 2; ++am) {
                        mma16(acc[am][bn], Ah[am], bp1[bn].x, bp1[bn].y);
                        mma16(acc[am][bn], Ah[am], bp1[bn].z, bp1[bn].w);
                        mma16(acc[am][bn], Al[am], bp1[bn].x, bp1[bn].y);
                    }
                }
            }
        }

        // epilogue: + bias2 -> out[:, 128:256]
        #pragma unroll
        for (int am = 0; am < 2; ++am) {
            #pragma unroll
            for (int bn = 0; bn < 4; ++bn) {
                int h = n0 + 8 * bn + 2 * t4;
                float2 bv = *(const float2*)&g_bias2[h];
                int e1 = e0 + m0 + 16 * am + g;
                if (e1 < E_TOT) {
                    *(float2*)&out[(size_t)e1 * 384 + 128 + h] =
                        make_float2(acc[am][bn][0] + bv.x, acc[am][bn][1] + bv.y);
                }
                int e2 = e1 + 8;
                if (e2 < E_TOT) {
                    *(float2*)&out[(size_t)e2 * 384 + 128 + h] =
                        make_float2(acc[am][bn][2] + bv.x, acc[am][bn][3] + bv.y);
                }
            }
        }
    }
}

// ---------------- launch ---------------------------------------------------
extern "C" void kernel_launch(void* const* d_in, const int* in_sizes, int n_in,
                              void* d_out, int out_size) {
    const float* ea   = (const float*)d_in[0];
    const float* gf   = (const float*)d_in[1];
    const int*   ei   = (const int*)d_in[2];
    const float* wq_l = (const float*)d_in[3];
    const float* wk_l = (const float*)d_in[4];
    const float* wv_l = (const float*)d_in[5];
    const float* bq_l = (const float*)d_in[6];
    const float* bv_l = (const float*)d_in[8];
    const float* wo_l = (const float*)d_in[9];
    const float* bo_l = (const float*)d_in[10];
    const float* wq_g = (const float*)d_in[11];
    const float* wk_g = (const float*)d_in[12];
    const float* wv_g = (const float*)d_in[13];
    const float* bq_g = (const float*)d_in[14];
    const float* bk_g = (const float*)d_in[15];
    const float* bv_g = (const float*)d_in[16];
    const float* wo_g = (const float*)d_in[17];
    const float* bo_g = (const float*)d_in[18];

    float* out        = (float*)d_out;
    float* out_pooled = out + (size_t)E_TOT * 384;
    float* out_attn   = out_pooled + 512;

    const int MAIN_SMEM = (2 * 64 * EA_U + 16640) * 4;   // 101376 B

    cudaFuncSetAttribute(k1_precompute,
                         cudaFuncAttributeMaxDynamicSharedMemorySize, 67584);
    cudaFuncSetAttribute(main_edge_kernel,
                         cudaFuncAttributeMaxDynamicSharedMemorySize, MAIN_SMEM);

    k1_precompute<<<POOL_BLKS + 386, 512, 67584>>>(gf, wq_l, wk_l, wv_l, wo_l,
                                                   bq_l, bv_l, bo_l,
                                                   wk_g, wv_g, wo_g, wq_g,
                                                   bk_g, bv_g, bq_g, out_pooled);
    main_edge_kernel<<<GRID_MAIN, 256, MAIN_SMEM>>>(ea, gf, ei, bo_g, out, out_attn);
}